// round 8
// baseline (speedup 1.0000x reference)
#include <cuda_runtime.h>
#include <stdint.h>

#define N_NODES  20000
#define N_EDGES  320000
#define F_IN     512
#define F_OUT    1024
#define N_GRAPHS 64

// ---------------- scratch (static device globals; no allocations) ----------
__device__ float g_xw[(size_t)N_NODES * F_OUT];   // gemm1 output (post bias/relu)
__device__ float g_h1[(size_t)N_NODES * F_OUT];   // agg outputs (512f then 1024f)
__device__ float g_h2[(size_t)N_NODES * F_OUT];   // gemm2 output
__device__ float g_w1t[(size_t)F_OUT * F_IN];     // W1^T tf32-rounded
__device__ float g_w2t[(size_t)F_OUT * F_OUT];    // W2^T tf32-rounded
__device__ float g_deg[N_NODES];
__device__ float g_dinv[N_NODES];
__device__ int   g_cnt_i[N_NODES];
__device__ int   g_rank[N_NODES];                 // scatter cursors (init = ptr)
__device__ int   g_ptr[N_NODES + 1];
__device__ int   g_csr_src[N_EDGES];
__device__ float g_csr_norm[N_EDGES];

// ---------------- small helpers ----------------
__device__ __forceinline__ float cvt_tf32(float x) {
    uint32_t r;
    asm("cvt.rna.tf32.f32 %0, %1;" : "=r"(r) : "f"(x));
    return __uint_as_float(r);
}

__device__ __forceinline__ void cp_async16(uint32_t saddr, const void* gptr, bool pred) {
    int sz = pred ? 16 : 0;           // sz=0 -> zero-fill 16B
    asm volatile("cp.async.cg.shared.global [%0], [%1], 16, %2;\n"
                 :: "r"(saddr), "l"(gptr), "r"(sz));
}
#define CP_COMMIT() asm volatile("cp.async.commit_group;\n" ::)
#define CP_WAIT(n)  asm volatile("cp.async.wait_group %0;\n" :: "n"(n))

__device__ __forceinline__ void ldsm_x4(uint32_t& r0, uint32_t& r1, uint32_t& r2,
                                        uint32_t& r3, uint32_t addr) {
    asm volatile("ldmatrix.sync.aligned.m8n8.x4.shared.b16 {%0,%1,%2,%3}, [%4];"
                 : "=r"(r0), "=r"(r1), "=r"(r2), "=r"(r3) : "r"(addr));
}

// ---------------- prep kernels ----------------
__global__ void k_init() {
    int i = blockIdx.x * blockDim.x + threadIdx.x;
    if (i < N_NODES) { g_deg[i] = 1.0f; g_cnt_i[i] = 0; }
}

__global__ void k_deg_cnt(const int* __restrict__ ei, const float* __restrict__ ew) {
    int e = blockIdx.x * blockDim.x + threadIdx.x;
    if (e < N_EDGES) {
        int d = ei[N_EDGES + e];
        atomicAdd(&g_deg[d], ew[e]);
        atomicAdd(&g_cnt_i[d], 1);
    }
}

// scan: dinv + exclusive prefix sum of counts -> ptr, rank (single block)
__global__ __launch_bounds__(1024)
void k_scan() {
    __shared__ int ps[1024];
    const int CH = (N_NODES + 1023) / 1024;  // 20
    int t = threadIdx.x;
    int base = t * CH;

    #pragma unroll
    for (int i = 0; i < CH; i++) {
        int idx = base + i;
        if (idx < N_NODES) {
            float d = g_deg[idx];
            g_dinv[idx] = (d > 0.0f) ? rsqrtf(d) : 0.0f;
        }
    }

    int s = 0;
    #pragma unroll
    for (int i = 0; i < CH; i++) {
        int idx = base + i;
        if (idx < N_NODES) s += g_cnt_i[idx];
    }
    ps[t] = s;
    __syncthreads();
    for (int off = 1; off < 1024; off <<= 1) {
        int v = (t >= off) ? ps[t - off] : 0;
        __syncthreads();
        ps[t] += v;
        __syncthreads();
    }
    int run = ps[t] - s;
    #pragma unroll
    for (int i = 0; i < CH; i++) {
        int idx = base + i;
        if (idx < N_NODES) { g_ptr[idx] = run; g_rank[idx] = run; run += g_cnt_i[idx]; }
    }
    if (t == 1023) g_ptr[N_NODES] = run;
}

__global__ void k_scatter(const int* __restrict__ ei, const float* __restrict__ ew) {
    int e = blockIdx.x * blockDim.x + threadIdx.x;
    if (e < N_EDGES) {
        int s = ei[e];
        int d = ei[N_EDGES + e];
        int pos = atomicAdd(&g_rank[d], 1);
        g_csr_src[pos]  = s;
        g_csr_norm[pos] = g_dinv[s] * ew[e] * g_dinv[d];
    }
}

// both weight transposes (tf32 RNA rounded) in one launch
__device__ __forceinline__ void tr_tile(const float* __restrict__ W,
                                        float* __restrict__ Wt, int R, int C) {
    __shared__ float s[32][33];
    int x  = blockIdx.x * 32 + threadIdx.x;
    int y0 = blockIdx.y * 32;
    #pragma unroll
    for (int i = 0; i < 32; i += 8)
        s[threadIdx.y + i][threadIdx.x] = cvt_tf32(W[(size_t)(y0 + threadIdx.y + i) * C + x]);
    __syncthreads();
    int xt  = blockIdx.y * 32 + threadIdx.x;
    int yt0 = blockIdx.x * 32;
    #pragma unroll
    for (int i = 0; i < 32; i += 8)
        Wt[(size_t)(yt0 + threadIdx.y + i) * R + xt] = s[threadIdx.x][threadIdx.y + i];
}

__global__ __launch_bounds__(256)
void k_tr2(const float* __restrict__ W1, float* __restrict__ W1t,
           const float* __restrict__ W2, float* __restrict__ W2t) {
    if (blockIdx.z == 0) {
        if (blockIdx.y < F_IN / 32) tr_tile(W1, W1t, F_IN, F_OUT);
    } else {
        tr_tile(W2, W2t, F_OUT, F_OUT);
    }
}

// ---------------- fused CSR aggregation (pre-GEMM): self + gather + cvt ---
template<int F, int DO_CVT>
__global__ __launch_bounds__(F / 4)
void k_agg(const float* __restrict__ in, float* __restrict__ out) {
    int n = blockIdx.x;
    int f = threadIdx.x * 4;

    float di = g_dinv[n];
    float s = di * di;
    float4 v = *(const float4*)(in + (size_t)n * F + f);
    float4 acc = make_float4(s * v.x, s * v.y, s * v.z, s * v.w);

    int e0 = g_ptr[n], e1 = g_ptr[n + 1];
    for (int e = e0; e < e1; e++) {
        int src = __ldg(&g_csr_src[e]);
        float w = __ldg(&g_csr_norm[e]);
        float4 u = *(const float4*)(in + (size_t)src * F + f);
        acc.x = fmaf(w, u.x, acc.x);
        acc.y = fmaf(w, u.y, acc.y);
        acc.z = fmaf(w, u.z, acc.z);
        acc.w = fmaf(w, u.w, acc.w);
    }
    if (DO_CVT) {
        acc.x = cvt_tf32(acc.x); acc.y = cvt_tf32(acc.y);
        acc.z = cvt_tf32(acc.z); acc.w = cvt_tf32(acc.w);
    }
    *(float4*)(out + (size_t)n * F + f) = acc;
}

// ---------------- tf32 mma.sync GEMM, 128x256 tile, fused bias+relu -----
// C[M, 1024] = relu(A[M,K] @ W[K,1024] + bias), Bt = W^T [1024, K] row-major.
// 8 warps (2m x 4n), warp tile 64x64, m16n8k8, 3-stage cp.async, BK=16.
// smem rows stride 20 floats (80B): ldmatrix 8-row groups conflict-free.

#define BM 128
#define BN 256
#define BK 16
#define PAD 20
#define A_STG (BM * PAD)                  // 2560 floats
#define B_STG (BN * PAD)                  // 5120 floats
#define GEMM_SMEM (3 * (A_STG + B_STG) * 4)   // 92160 B

__device__ __forceinline__ void mma_tf32(float c[4], const uint32_t a[4],
                                         uint32_t b0, uint32_t b1) {
    asm volatile(
        "mma.sync.aligned.m16n8k8.row.col.f32.tf32.tf32.f32 "
        "{%0,%1,%2,%3}, {%4,%5,%6,%7}, {%8,%9}, {%0,%1,%2,%3};"
        : "+f"(c[0]), "+f"(c[1]), "+f"(c[2]), "+f"(c[3])
        : "r"(a[0]), "r"(a[1]), "r"(a[2]), "r"(a[3]), "r"(b0), "r"(b1));
}

__global__ __launch_bounds__(256, 1)
void k_gemm(const float* __restrict__ A, const float* __restrict__ Bt,
            float* __restrict__ C, const float* __restrict__ bias, int M, int K) {
    extern __shared__ float smem[];

    const int tid  = threadIdx.x;
    const int lane = tid & 31;
    const int warp = tid >> 5;
    const int wm = warp & 1;
    const int wn = warp >> 1;
    const int g = lane >> 2;
    const int t = lane & 3;

    const int brow = blockIdx.y * BM;
    const int bcol = blockIdx.x * BN;
    const int rmaxA = M - brow;

    uint32_t sbase = (uint32_t)__cvta_generic_to_shared(smem);
    uint32_t sA[3], sB[3];
    #pragma unroll
    for (int s = 0; s < 3; s++) {
        sA[s] = sbase + (uint32_t)(s * (A_STG + B_STG)) * 4;
        sB[s] = sA[s] + A_STG * 4;
    }

    const float* Ag = A + (size_t)brow * K;
    const float* Bg = Bt + (size_t)bcol * K;

    // fill descriptors: A 512 chunks (2/thread), B 1024 chunks (4/thread)
    const int a_r0 = tid >> 2,         a_c = tid & 3;
    const int a_r1 = (tid + 256) >> 2;

    // ldmatrix lane addressing (same mapping validated in R7)
    const int la_row = wm * 64 + ((lane >> 3) & 1) * 8 + (lane & 7);
    const int la_col = ((lane >> 4) & 1) * 4;
    const int lb_row = wn * 64 + ((lane >> 4) & 1) * 8 + (lane & 7);
    const int lb_col = ((lane >> 3) & 1) * 4;

    const int KT = K >> 4;

    #define FILL(st, kt_) do {                                                  \
        int k0_ = (kt_) * BK;                                                   \
        cp_async16(sA[st] + (a_r0 * PAD + a_c * 4) * 4,                         \
                   Ag + (size_t)a_r0 * K + k0_ + a_c * 4, a_r0 < rmaxA);        \
        cp_async16(sA[st] + (a_r1 * PAD + a_c * 4) * 4,                         \
                   Ag + (size_t)a_r1 * K + k0_ + a_c * 4, a_r1 < rmaxA);        \
        _Pragma("unroll")                                                       \
        for (int u_ = 0; u_ < 4; u_++) {                                        \
            int ch_ = tid + u_ * 256;                                           \
            int r_ = ch_ >> 2, c_ = ch_ & 3;                                    \
            cp_async16(sB[st] + (r_ * PAD + c_ * 4) * 4,                        \
                       Bg + (size_t)r_ * K + k0_ + c_ * 4, true);               \
        }                                                                       \
        CP_COMMIT();                                                            \
    } while (0)

    FILL(0, 0);
    FILL(1, 1);

    float acc[4][8][4];
    #pragma unroll
    for (int i = 0; i < 4; i++)
        #pragma unroll
        for (int j = 0; j < 8; j++)
            #pragma unroll
            for (int r = 0; r < 4; r++) acc[i][j][r] = 0.0f;

    for (int kt = 0; kt < KT; kt++) {
        if (kt + 1 < KT) { CP_WAIT(1); } else { CP_WAIT(0); }
        __syncthreads();

        int buf = kt % 3;
        uint32_t aab = sA[buf] + (la_row * PAD + la_col) * 4;
        uint32_t bab = sB[buf] + (lb_row * PAD + lb_col) * 4;

        #pragma unroll
        for (int ks = 0; ks < 2; ks++) {
            const int kb = ks * 8;
            uint32_t af[4][4];
            #pragma unroll
            for (int i = 0; i < 4; i++)
                ldsm_x4(af[i][0], af[i][1], af[i][2], af[i][3],
                        aab + (i * 16 * PAD + kb) * 4);
            uint32_t bf[4][4];
            #pragma unroll
            for (int j2 = 0; j2 < 4; j2++)
                ldsm_x4(bf[j2][0], bf[j2][1], bf[j2][2], bf[j2][3],
                        bab + (j2 * 16 * PAD + kb) * 4);
            #pragma unroll
            for (int i = 0; i < 4; i++) {
                #pragma unroll
                for (int j = 0; j < 8; j++) {
                    const uint32_t* bp = &bf[j >> 1][(j & 1) * 2];
                    mma_tf32(acc[i][j], af[i], bp[0], bp[1]);
                }
            }
        }

        if (kt + 2 < KT) {
            int nb = (kt + 2) % 3;
            FILL(nb, kt + 2);
        }
    }
    #undef FILL

    // epilogue: bias + relu
    #pragma unroll
    for (int j = 0; j < 8; j++) {
        int c0 = bcol + wn * 64 + j * 8 + 2 * t;
        float2 bb = *(const float2*)(bias + c0);
        #pragma unroll
        for (int i = 0; i < 4; i++) {
            int r0 = brow + wm * 64 + i * 16 + g;
            int r1 = r0 + 8;
            if (r0 < M) {
                float2 v = make_float2(fmaxf(acc[i][j][0] + bb.x, 0.0f),
                                       fmaxf(acc[i][j][1] + bb.y, 0.0f));
                *(float2*)(C + (size_t)r0 * F_OUT + c0) = v;
            }
            if (r1 < M) {
                float2 v = make_float2(fmaxf(acc[i][j][2] + bb.x, 0.0f),
                                       fmaxf(acc[i][j][3] + bb.y, 0.0f));
                *(float2*)(C + (size_t)r1 * F_OUT + c0) = v;
            }
        }
    }
}

// ---------------- segmented mean pooling (batch is sorted) ---------------
__global__ __launch_bounds__(256)
void k_pool(const int* __restrict__ batch, const float* __restrict__ h,
            float* __restrict__ out) {
    int gph = blockIdx.x;
    int f = threadIdx.x * 4;

    int lo = 0, hi = N_NODES;
    while (lo < hi) { int m = (lo + hi) >> 1; if (batch[m] < gph) lo = m + 1; else hi = m; }
    int s = lo;
    hi = N_NODES;
    while (lo < hi) { int m = (lo + hi) >> 1; if (batch[m] < gph + 1) lo = m + 1; else hi = m; }
    int e = lo;

    float4 acc = make_float4(0.f, 0.f, 0.f, 0.f);
    for (int n = s; n < e; n++) {
        float4 v = *(const float4*)(h + (size_t)n * F_OUT + f);
        acc.x += v.x; acc.y += v.y; acc.z += v.z; acc.w += v.w;
    }
    float c = 1.0f / fmaxf((float)(e - s), 1.0f);
    acc.x *= c; acc.y *= c; acc.z *= c; acc.w *= c;
    *(float4*)(out + (size_t)gph * F_OUT + f) = acc;
}

// ---------------- launch ----------------
extern "C" void kernel_launch(void* const* d_in, const int* in_sizes, int n_in,
                              void* d_out, int out_size) {
    const float* x     = (const float*)d_in[0];
    const int*   ei    = (const int*)d_in[1];
    const float* ew    = (const float*)d_in[2];
    const int*   batch = (const int*)d_in[3];
    const float* W1    = (const float*)d_in[4];
    const float* b1    = (const float*)d_in[5];
    const float* W2    = (const float*)d_in[6];
    const float* b2    = (const float*)d_in[7];
    float* out = (float*)d_out;

    float *xw, *h1, *h2, *w1t, *w2t;
    cudaGetSymbolAddress((void**)&xw,  g_xw);
    cudaGetSymbolAddress((void**)&h1,  g_h1);
    cudaGetSymbolAddress((void**)&h2,  g_h2);
    cudaGetSymbolAddress((void**)&w1t, g_w1t);
    cudaGetSymbolAddress((void**)&w2t, g_w2t);

    static int smem_set = 0;
    if (!smem_set) {
        cudaFuncSetAttribute(k_gemm,
                             cudaFuncAttributeMaxDynamicSharedMemorySize, GEMM_SMEM);
        smem_set = 1;
    }

    const int T = 256;

    // ---- graph prep (5 launches; agg1 lands in the ncu -s 5 window) ----
    k_init<<<(N_NODES + T - 1) / T, T>>>();
    k_deg_cnt<<<(N_EDGES + T - 1) / T, T>>>(ei, ew);
    k_scan<<<1, 1024>>>();
    k_scatter<<<(N_EDGES + T - 1) / T, T>>>(ei, ew);
    k_tr2<<<dim3(F_OUT / 32, F_OUT / 32, 2), dim3(32, 8)>>>(W1, w1t, W2, w2t);

    dim3 gg(F_OUT / BN, (N_NODES + BM - 1) / BM);

    // ---- layer 1: (A x) W1 + b1, relu ----
    k_agg<F_IN, 1><<<N_NODES, F_IN / 4>>>(x, h1);            // 512f agg, tf32-cvt
    k_gemm<<<gg, 256, GEMM_SMEM>>>(h1, w1t, xw, b1, N_NODES, F_IN);

    // ---- layer 2: (A h1) W2 + b2, relu ----
    k_agg<F_OUT, 1><<<N_NODES, F_OUT / 4>>>(xw, h1);         // 1024f agg, tf32-cvt
    k_gemm<<<gg, 256, GEMM_SMEM>>>(h1, w2t, h2, b2, N_NODES, F_OUT);

    // ---- mean pool ----
    k_pool<<<N_GRAPHS, 256>>>(batch, h2, out);
}

// round 9
// speedup vs baseline: 1.1528x; 1.1528x over previous
#include <cuda_runtime.h>
#include <stdint.h>

#define N_NODES  20000
#define N_EDGES  320000
#define F_IN     512
#define F_OUT    1024
#define N_GRAPHS 64

// ---------------- scratch (static device globals; no allocations) ----------
__device__ float g_xw[(size_t)N_NODES * F_OUT];   // gemm1 output (post bias/relu)
__device__ float g_h1[(size_t)N_NODES * F_OUT];   // agg outputs (512f then 1024f)
__device__ float g_h2[(size_t)N_NODES * F_OUT];   // gemm2 output
__device__ float g_w1t[(size_t)F_OUT * F_IN];     // W1^T tf32-rounded
__device__ float g_w2t[(size_t)F_OUT * F_OUT];    // W2^T tf32-rounded
__device__ float g_deg[N_NODES];
__device__ float g_dinv[N_NODES];
__device__ int   g_cnt_i[N_NODES];
__device__ int   g_rank[N_NODES];                 // scatter cursors (init = ptr)
__device__ int   g_ptr[N_NODES + 1];
__device__ int   g_csr_src[N_EDGES];
__device__ float g_csr_norm[N_EDGES];

// ---------------- small helpers ----------------
__device__ __forceinline__ float cvt_tf32(float x) {
    uint32_t r;
    asm("cvt.rna.tf32.f32 %0, %1;" : "=r"(r) : "f"(x));
    return __uint_as_float(r);
}

__device__ __forceinline__ void cp_async16(uint32_t saddr, const void* gptr, bool pred) {
    int sz = pred ? 16 : 0;           // sz=0 -> zero-fill 16B
    asm volatile("cp.async.cg.shared.global [%0], [%1], 16, %2;\n"
                 :: "r"(saddr), "l"(gptr), "r"(sz));
}
#define CP_COMMIT() asm volatile("cp.async.commit_group;\n" ::)
#define CP_WAIT(n)  asm volatile("cp.async.wait_group %0;\n" :: "n"(n))

__device__ __forceinline__ void ldsm_x4(uint32_t& r0, uint32_t& r1, uint32_t& r2,
                                        uint32_t& r3, uint32_t addr) {
    asm volatile("ldmatrix.sync.aligned.m8n8.x4.shared.b16 {%0,%1,%2,%3}, [%4];"
                 : "=r"(r0), "=r"(r1), "=r"(r2), "=r"(r3) : "r"(addr));
}

// ---------------- prep kernels ----------------
__global__ void k_init() {
    int i = blockIdx.x * blockDim.x + threadIdx.x;
    if (i < N_NODES) { g_deg[i] = 1.0f; g_cnt_i[i] = 0; }
}

__global__ void k_deg_cnt(const int* __restrict__ ei, const float* __restrict__ ew) {
    int e = blockIdx.x * blockDim.x + threadIdx.x;
    if (e < N_EDGES) {
        int d = ei[N_EDGES + e];
        atomicAdd(&g_deg[d], ew[e]);
        atomicAdd(&g_cnt_i[d], 1);
    }
}

// scan: dinv + exclusive prefix sum of counts -> ptr, rank (single block)
__global__ __launch_bounds__(1024)
void k_scan() {
    __shared__ int ps[1024];
    const int CH = (N_NODES + 1023) / 1024;  // 20
    int t = threadIdx.x;
    int base = t * CH;

    #pragma unroll
    for (int i = 0; i < CH; i++) {
        int idx = base + i;
        if (idx < N_NODES) {
            float d = g_deg[idx];
            g_dinv[idx] = (d > 0.0f) ? rsqrtf(d) : 0.0f;
        }
    }

    int s = 0;
    #pragma unroll
    for (int i = 0; i < CH; i++) {
        int idx = base + i;
        if (idx < N_NODES) s += g_cnt_i[idx];
    }
    ps[t] = s;
    __syncthreads();
    for (int off = 1; off < 1024; off <<= 1) {
        int v = (t >= off) ? ps[t - off] : 0;
        __syncthreads();
        ps[t] += v;
        __syncthreads();
    }
    int run = ps[t] - s;
    #pragma unroll
    for (int i = 0; i < CH; i++) {
        int idx = base + i;
        if (idx < N_NODES) { g_ptr[idx] = run; g_rank[idx] = run; run += g_cnt_i[idx]; }
    }
    if (t == 1023) g_ptr[N_NODES] = run;
}

__global__ void k_scatter(const int* __restrict__ ei, const float* __restrict__ ew) {
    int e = blockIdx.x * blockDim.x + threadIdx.x;
    if (e < N_EDGES) {
        int s = ei[e];
        int d = ei[N_EDGES + e];
        int pos = atomicAdd(&g_rank[d], 1);
        g_csr_src[pos]  = s;
        g_csr_norm[pos] = g_dinv[s] * ew[e] * g_dinv[d];
    }
}

// both weight transposes (tf32 RNA rounded) in one launch
__device__ __forceinline__ void tr_tile(const float* __restrict__ W,
                                        float* __restrict__ Wt, int R, int C) {
    __shared__ float s[32][33];
    int x  = blockIdx.x * 32 + threadIdx.x;
    int y0 = blockIdx.y * 32;
    #pragma unroll
    for (int i = 0; i < 32; i += 8)
        s[threadIdx.y + i][threadIdx.x] = cvt_tf32(W[(size_t)(y0 + threadIdx.y + i) * C + x]);
    __syncthreads();
    int xt  = blockIdx.y * 32 + threadIdx.x;
    int yt0 = blockIdx.x * 32;
    #pragma unroll
    for (int i = 0; i < 32; i += 8)
        Wt[(size_t)(yt0 + threadIdx.y + i) * R + xt] = s[threadIdx.x][threadIdx.y + i];
}

__global__ __launch_bounds__(256)
void k_tr2(const float* __restrict__ W1, float* __restrict__ W1t,
           const float* __restrict__ W2, float* __restrict__ W2t) {
    if (blockIdx.z == 0) {
        if (blockIdx.y < F_IN / 32) tr_tile(W1, W1t, F_IN, F_OUT);
    } else {
        tr_tile(W2, W2t, F_OUT, F_OUT);
    }
}

// ---------------- fused CSR aggregation (pre-GEMM): self + gather + cvt ---
template<int F, int DO_CVT>
__global__ __launch_bounds__(F / 4)
void k_agg(const float* __restrict__ in, float* __restrict__ out) {
    int n = blockIdx.x;
    int f = threadIdx.x * 4;

    float di = g_dinv[n];
    float s = di * di;
    float4 v = *(const float4*)(in + (size_t)n * F + f);
    float4 acc = make_float4(s * v.x, s * v.y, s * v.z, s * v.w);

    int e0 = g_ptr[n], e1 = g_ptr[n + 1];
    for (int e = e0; e < e1; e++) {
        int src = __ldg(&g_csr_src[e]);
        float w = __ldg(&g_csr_norm[e]);
        float4 u = *(const float4*)(in + (size_t)src * F + f);
        acc.x = fmaf(w, u.x, acc.x);
        acc.y = fmaf(w, u.y, acc.y);
        acc.z = fmaf(w, u.z, acc.z);
        acc.w = fmaf(w, u.w, acc.w);
    }
    if (DO_CVT) {
        acc.x = cvt_tf32(acc.x); acc.y = cvt_tf32(acc.y);
        acc.z = cvt_tf32(acc.z); acc.w = cvt_tf32(acc.w);
    }
    *(float4*)(out + (size_t)n * F + f) = acc;
}

// ---------------- tf32 mma.sync GEMM, 128x128 tile, 4 warps 2x2 ---------
// C[M, 1024] = relu(A[M,K] @ W[K,1024] + bias), Bt = W^T [1024, K] row-major.
// Warp tile 64x64, m16n8k8, 3-stage cp.async, BK=16, 2 CTAs/SM.
// smem rows stride 20 floats (80B): ldmatrix 8-row groups conflict-free.

#define BM 128
#define BN 128
#define BK 16
#define PAD 20
#define A_STG (BM * PAD)                      // 2560 floats
#define B_STG (BN * PAD)                      // 2560 floats
#define GEMM_SMEM (3 * (A_STG + B_STG) * 4)   // 61440 B

__device__ __forceinline__ void mma_tf32(float c[4], const uint32_t a[4],
                                         uint32_t b0, uint32_t b1) {
    asm volatile(
        "mma.sync.aligned.m16n8k8.row.col.f32.tf32.tf32.f32 "
        "{%0,%1,%2,%3}, {%4,%5,%6,%7}, {%8,%9}, {%0,%1,%2,%3};"
        : "+f"(c[0]), "+f"(c[1]), "+f"(c[2]), "+f"(c[3])
        : "r"(a[0]), "r"(a[1]), "r"(a[2]), "r"(a[3]), "r"(b0), "r"(b1));
}

__global__ __launch_bounds__(128, 2)
void k_gemm(const float* __restrict__ A, const float* __restrict__ Bt,
            float* __restrict__ C, const float* __restrict__ bias, int M, int K) {
    extern __shared__ float smem[];

    const int tid  = threadIdx.x;
    const int lane = tid & 31;
    const int warp = tid >> 5;    // 0..3
    const int wm = warp & 1;      // 2 m-warps
    const int wn = warp >> 1;     // 2 n-warps
    const int g = lane >> 2;
    const int t = lane & 3;

    const int brow = blockIdx.y * BM;
    const int bcol = blockIdx.x * BN;
    const int rmaxA = M - brow;

    uint32_t sbase = (uint32_t)__cvta_generic_to_shared(smem);
    uint32_t sA[3], sB[3];
    #pragma unroll
    for (int s = 0; s < 3; s++) {
        sA[s] = sbase + (uint32_t)(s * (A_STG + B_STG)) * 4;
        sB[s] = sA[s] + A_STG * 4;
    }

    const float* Ag = A + (size_t)brow * K;
    const float* Bg = Bt + (size_t)bcol * K;

    // ldmatrix lane addressing (64x64 warp tile; mapping validated R7/R8)
    const int la_row = wm * 64 + ((lane >> 3) & 1) * 8 + (lane & 7);
    const int la_col = ((lane >> 4) & 1) * 4;
    const int lb_row = wn * 64 + ((lane >> 4) & 1) * 8 + (lane & 7);
    const int lb_col = ((lane >> 3) & 1) * 4;

    const int KT = K >> 4;

    // fill: A and B each 512 16B-chunks, 128 threads -> 4 chunks each
    #define FILL(st, kt_) do {                                                  \
        int k0_ = (kt_) * BK;                                                   \
        _Pragma("unroll")                                                       \
        for (int u_ = 0; u_ < 4; u_++) {                                        \
            int ch_ = tid + u_ * 128;                                           \
            int r_ = ch_ >> 2, c_ = ch_ & 3;                                    \
            cp_async16(sA[st] + (r_ * PAD + c_ * 4) * 4,                        \
                       Ag + (size_t)r_ * K + k0_ + c_ * 4, r_ < rmaxA);         \
            cp_async16(sB[st] + (r_ * PAD + c_ * 4) * 4,                        \
                       Bg + (size_t)r_ * K + k0_ + c_ * 4, true);               \
        }                                                                       \
        CP_COMMIT();                                                            \
    } while (0)

    FILL(0, 0);
    FILL(1, 1);

    float acc[4][8][4];
    #pragma unroll
    for (int i = 0; i < 4; i++)
        #pragma unroll
        for (int j = 0; j < 8; j++)
            #pragma unroll
            for (int r = 0; r < 4; r++) acc[i][j][r] = 0.0f;

    for (int kt = 0; kt < KT; kt++) {
        if (kt + 1 < KT) { CP_WAIT(1); } else { CP_WAIT(0); }
        __syncthreads();

        int buf = kt % 3;
        uint32_t aab = sA[buf] + (la_row * PAD + la_col) * 4;
        uint32_t bab = sB[buf] + (lb_row * PAD + lb_col) * 4;

        #pragma unroll
        for (int ks = 0; ks < 2; ks++) {
            const int kb = ks * 8;
            uint32_t af[4][4];
            #pragma unroll
            for (int i = 0; i < 4; i++)
                ldsm_x4(af[i][0], af[i][1], af[i][2], af[i][3],
                        aab + (i * 16 * PAD + kb) * 4);
            uint32_t bf[4][4];
            #pragma unroll
            for (int j2 = 0; j2 < 4; j2++)
                ldsm_x4(bf[j2][0], bf[j2][1], bf[j2][2], bf[j2][3],
                        bab + (j2 * 16 * PAD + kb) * 4);
            #pragma unroll
            for (int i = 0; i < 4; i++) {
                #pragma unroll
                for (int j = 0; j < 8; j++) {
                    const uint32_t* bp = &bf[j >> 1][(j & 1) * 2];
                    mma_tf32(acc[i][j], af[i], bp[0], bp[1]);
                }
            }
        }

        if (kt + 2 < KT) {
            int nb = (kt + 2) % 3;
            FILL(nb, kt + 2);
        }
    }
    #undef FILL

    // epilogue: bias + relu
    #pragma unroll
    for (int j = 0; j < 8; j++) {
        int c0 = bcol + wn * 64 + j * 8 + 2 * t;
        float2 bb = *(const float2*)(bias + c0);
        #pragma unroll
        for (int i = 0; i < 4; i++) {
            int r0 = brow + wm * 64 + i * 16 + g;
            int r1 = r0 + 8;
            if (r0 < M) {
                float2 v = make_float2(fmaxf(acc[i][j][0] + bb.x, 0.0f),
                                       fmaxf(acc[i][j][1] + bb.y, 0.0f));
                *(float2*)(C + (size_t)r0 * F_OUT + c0) = v;
            }
            if (r1 < M) {
                float2 v = make_float2(fmaxf(acc[i][j][2] + bb.x, 0.0f),
                                       fmaxf(acc[i][j][3] + bb.y, 0.0f));
                *(float2*)(C + (size_t)r1 * F_OUT + c0) = v;
            }
        }
    }
}

// ---------------- segmented mean pooling (batch is sorted) ---------------
__global__ __launch_bounds__(256)
void k_pool(const int* __restrict__ batch, const float* __restrict__ h,
            float* __restrict__ out) {
    int gph = blockIdx.x;
    int f = threadIdx.x * 4;

    int lo = 0, hi = N_NODES;
    while (lo < hi) { int m = (lo + hi) >> 1; if (batch[m] < gph) lo = m + 1; else hi = m; }
    int s = lo;
    hi = N_NODES;
    while (lo < hi) { int m = (lo + hi) >> 1; if (batch[m] < gph + 1) lo = m + 1; else hi = m; }
    int e = lo;

    float4 acc = make_float4(0.f, 0.f, 0.f, 0.f);
    for (int n = s; n < e; n++) {
        float4 v = *(const float4*)(h + (size_t)n * F_OUT + f);
        acc.x += v.x; acc.y += v.y; acc.z += v.z; acc.w += v.w;
    }
    float c = 1.0f / fmaxf((float)(e - s), 1.0f);
    acc.x *= c; acc.y *= c; acc.z *= c; acc.w *= c;
    *(float4*)(out + (size_t)gph * F_OUT + f) = acc;
}

// ---------------- launch ----------------
extern "C" void kernel_launch(void* const* d_in, const int* in_sizes, int n_in,
                              void* d_out, int out_size) {
    const float* x     = (const float*)d_in[0];
    const int*   ei    = (const int*)d_in[1];
    const float* ew    = (const float*)d_in[2];
    const int*   batch = (const int*)d_in[3];
    const float* W1    = (const float*)d_in[4];
    const float* b1    = (const float*)d_in[5];
    const float* W2    = (const float*)d_in[6];
    const float* b2    = (const float*)d_in[7];
    float* out = (float*)d_out;

    float *xw, *h1, *h2, *w1t, *w2t;
    cudaGetSymbolAddress((void**)&xw,  g_xw);
    cudaGetSymbolAddress((void**)&h1,  g_h1);
    cudaGetSymbolAddress((void**)&h2,  g_h2);
    cudaGetSymbolAddress((void**)&w1t, g_w1t);
    cudaGetSymbolAddress((void**)&w2t, g_w2t);

    static int smem_set = 0;
    if (!smem_set) {
        cudaFuncSetAttribute(k_gemm,
                             cudaFuncAttributeMaxDynamicSharedMemorySize, GEMM_SMEM);
        smem_set = 1;
    }

    const int T = 256;

    // ---- graph prep ----
    k_init<<<(N_NODES + T - 1) / T, T>>>();
    k_deg_cnt<<<(N_EDGES + T - 1) / T, T>>>(ei, ew);
    k_scan<<<1, 1024>>>();
    k_scatter<<<(N_EDGES + T - 1) / T, T>>>(ei, ew);
    k_tr2<<<dim3(F_OUT / 32, F_OUT / 32, 2), dim3(32, 8)>>>(W1, w1t, W2, w2t);

    dim3 gg(F_OUT / BN, (N_NODES + BM - 1) / BM);

    // ---- layer 1: (A x) W1 + b1, relu ----
    k_agg<F_IN, 1><<<N_NODES, F_IN / 4>>>(x, h1);            // 512f agg, tf32-cvt
    k_gemm<<<gg, 128, GEMM_SMEM>>>(h1, w1t, xw, b1, N_NODES, F_IN);

    // ---- layer 2: (A h1) W2 + b2, relu ----
    k_agg<F_OUT, 1><<<N_NODES, F_OUT / 4>>>(xw, h1);         // 1024f agg, tf32-cvt
    k_gemm<<<gg, 128, GEMM_SMEM>>>(h1, w2t, h2, b2, N_NODES, F_OUT);

    // ---- mean pool ----
    k_pool<<<N_GRAPHS, 256>>>(batch, h2, out);
}

// round 10
// speedup vs baseline: 1.2449x; 1.0799x over previous
#include <cuda_runtime.h>
#include <cuda_fp16.h>
#include <stdint.h>

#define N_NODES  20000
#define N_EDGES  320000
#define F_IN     512
#define F_OUT    1024
#define N_GRAPHS 64

// ---------------- scratch (static device globals; no allocations) ----------
// g_xw: fp16 xw [N,1024] (41MB of the 82MB)
__device__ float g_xw[(size_t)N_NODES * F_OUT];
__device__ float g_h1[(size_t)N_NODES * F_OUT];   // agg outputs fp32 (512f/1024f)
// g_h2: x_h fp16 [N,512] early; later gemm2 fp32 output [N,1024] (disjoint in time)
__device__ float g_h2[(size_t)N_NODES * F_OUT];
__device__ float g_w1t[(size_t)F_OUT * F_IN];     // W1^T tf32-rounded
__device__ float g_w2t[(size_t)F_OUT * F_OUT];    // W2^T tf32-rounded
__device__ float g_deg[N_NODES];                  // zero at entry (re-zeroed by pool)
__device__ float g_dinv[N_NODES];
__device__ int   g_cnt_i[N_NODES];                // zero at entry (re-zeroed by pool)
__device__ int   g_rank[N_NODES];
__device__ int   g_ptr[N_NODES + 1];
__device__ int   g_csr_src[N_EDGES];
__device__ float g_csr_norm[N_EDGES];

// ---------------- small helpers ----------------
__device__ __forceinline__ float cvt_tf32(float x) {
    uint32_t r;
    asm("cvt.rna.tf32.f32 %0, %1;" : "=r"(r) : "f"(x));
    return __uint_as_float(r);
}

__device__ __forceinline__ void cp_async16(uint32_t saddr, const void* gptr, bool pred) {
    int sz = pred ? 16 : 0;           // sz=0 -> zero-fill 16B
    asm volatile("cp.async.cg.shared.global [%0], [%1], 16, %2;\n"
                 :: "r"(saddr), "l"(gptr), "r"(sz));
}
#define CP_COMMIT() asm volatile("cp.async.commit_group;\n" ::)
#define CP_WAIT(n)  asm volatile("cp.async.wait_group %0;\n" :: "n"(n))

__device__ __forceinline__ void ldsm_x4(uint32_t& r0, uint32_t& r1, uint32_t& r2,
                                        uint32_t& r3, uint32_t addr) {
    asm volatile("ldmatrix.sync.aligned.m8n8.x4.shared.b16 {%0,%1,%2,%3}, [%4];"
                 : "=r"(r0), "=r"(r1), "=r"(r2), "=r"(r3) : "r"(addr));
}

// ---------------- L1: fused degree-count + x->fp16 convert ----------------
#define EDGE_BLOCKS ((N_EDGES + 255) / 256)               // 1250
#define XCVT4 (N_NODES * F_IN / 4)                        // float4 count
#define XCVT_BLOCKS ((XCVT4 + 255) / 256)                 // 10000

__global__ __launch_bounds__(256)
void k_pre(const int* __restrict__ ei, const float* __restrict__ ew,
           const float* __restrict__ x, __half* __restrict__ xh) {
    int b = blockIdx.x;
    if (b < EDGE_BLOCKS) {
        int e = b * 256 + threadIdx.x;
        if (e < N_EDGES) {
            int d = ei[N_EDGES + e];
            atomicAdd(&g_deg[d], ew[e]);
            atomicAdd(&g_cnt_i[d], 1);
        }
    } else {
        int i = (b - EDGE_BLOCKS) * 256 + threadIdx.x;
        if (i < XCVT4) {
            float4 v = ((const float4*)x)[i];
            __half2 h0 = __floats2half2_rn(v.x, v.y);
            __half2 h1 = __floats2half2_rn(v.z, v.w);
            uint2 p;
            p.x = *reinterpret_cast<uint32_t*>(&h0);
            p.y = *reinterpret_cast<uint32_t*>(&h1);
            ((uint2*)xh)[i] = p;
        }
    }
}

// L2: dinv (with +1 self loop) + exclusive prefix sum -> ptr, rank
__global__ __launch_bounds__(1024)
void k_scan() {
    __shared__ int ps[1024];
    const int CH = (N_NODES + 1023) / 1024;  // 20
    int t = threadIdx.x;
    int base = t * CH;

    #pragma unroll
    for (int i = 0; i < CH; i++) {
        int idx = base + i;
        if (idx < N_NODES) {
            float d = g_deg[idx] + 1.0f;    // + self-loop weight
            g_dinv[idx] = rsqrtf(d);        // d >= 1 always
        }
    }

    int s = 0;
    #pragma unroll
    for (int i = 0; i < CH; i++) {
        int idx = base + i;
        if (idx < N_NODES) s += g_cnt_i[idx];
    }
    ps[t] = s;
    __syncthreads();
    for (int off = 1; off < 1024; off <<= 1) {
        int v = (t >= off) ? ps[t - off] : 0;
        __syncthreads();
        ps[t] += v;
        __syncthreads();
    }
    int run = ps[t] - s;
    #pragma unroll
    for (int i = 0; i < CH; i++) {
        int idx = base + i;
        if (idx < N_NODES) { g_ptr[idx] = run; g_rank[idx] = run; run += g_cnt_i[idx]; }
    }
    if (t == 1023) g_ptr[N_NODES] = run;
}

// L3: CSR scatter
__global__ void k_scatter(const int* __restrict__ ei, const float* __restrict__ ew) {
    int e = blockIdx.x * blockDim.x + threadIdx.x;
    if (e < N_EDGES) {
        int s = ei[e];
        int d = ei[N_EDGES + e];
        int pos = atomicAdd(&g_rank[d], 1);
        g_csr_src[pos]  = s;
        g_csr_norm[pos] = g_dinv[s] * ew[e] * g_dinv[d];
    }
}

// ---------------- fused CSR aggregation, fp16 in -> tf32-fp32 out --------
template<int F>
__global__ __launch_bounds__(F / 4)
void k_agg_h(const __half* __restrict__ in, float* __restrict__ out) {
    int n = blockIdx.x;
    int f = threadIdx.x * 4;

    float di = g_dinv[n];
    float s = di * di;

    uint2 raw = *(const uint2*)(in + (size_t)n * F + f);
    float2 p0 = __half22float2(*reinterpret_cast<__half2*>(&raw.x));
    float2 p1 = __half22float2(*reinterpret_cast<__half2*>(&raw.y));
    float4 acc = make_float4(s * p0.x, s * p0.y, s * p1.x, s * p1.y);

    int e0 = g_ptr[n], e1 = g_ptr[n + 1];
    for (int e = e0; e < e1; e++) {
        int src = __ldg(&g_csr_src[e]);
        float w = __ldg(&g_csr_norm[e]);
        uint2 r = *(const uint2*)(in + (size_t)src * F + f);
        float2 u0 = __half22float2(*reinterpret_cast<__half2*>(&r.x));
        float2 u1 = __half22float2(*reinterpret_cast<__half2*>(&r.y));
        acc.x = fmaf(w, u0.x, acc.x);
        acc.y = fmaf(w, u0.y, acc.y);
        acc.z = fmaf(w, u1.x, acc.z);
        acc.w = fmaf(w, u1.y, acc.w);
    }
    acc.x = cvt_tf32(acc.x); acc.y = cvt_tf32(acc.y);
    acc.z = cvt_tf32(acc.z); acc.w = cvt_tf32(acc.w);
    *(float4*)(out + (size_t)n * F + f) = acc;
}

// ---------------- weight transposes (tf32 RNA) ----------------
__device__ __forceinline__ void tr_tile(const float* __restrict__ W,
                                        float* __restrict__ Wt, int R, int C) {
    __shared__ float s[32][33];
    int x  = blockIdx.x * 32 + threadIdx.x;
    int y0 = blockIdx.y * 32;
    #pragma unroll
    for (int i = 0; i < 32; i += 8)
        s[threadIdx.y + i][threadIdx.x] = cvt_tf32(W[(size_t)(y0 + threadIdx.y + i) * C + x]);
    __syncthreads();
    int xt  = blockIdx.y * 32 + threadIdx.x;
    int yt0 = blockIdx.x * 32;
    #pragma unroll
    for (int i = 0; i < 32; i += 8)
        Wt[(size_t)(yt0 + threadIdx.y + i) * R + xt] = s[threadIdx.x][threadIdx.y + i];
}

__global__ __launch_bounds__(256)
void k_tr2(const float* __restrict__ W1, float* __restrict__ W1t,
           const float* __restrict__ W2, float* __restrict__ W2t) {
    if (blockIdx.z == 0) {
        if (blockIdx.y < F_IN / 32) tr_tile(W1, W1t, F_IN, F_OUT);
    } else {
        tr_tile(W2, W2t, F_OUT, F_OUT);
    }
}

// ---------------- tf32 mma.sync GEMM, 128x128, 4 warps 2x2, 2 CTAs/SM ----
// C = relu(A @ W + bias); OT=float or __half output.
#define BM 128
#define BN 128
#define BK 16
#define PAD 20
#define A_STG (BM * PAD)
#define B_STG (BN * PAD)
#define GEMM_SMEM (3 * (A_STG + B_STG) * 4)   // 61440 B

__device__ __forceinline__ void mma_tf32(float c[4], const uint32_t a[4],
                                         uint32_t b0, uint32_t b1) {
    asm volatile(
        "mma.sync.aligned.m16n8k8.row.col.f32.tf32.tf32.f32 "
        "{%0,%1,%2,%3}, {%4,%5,%6,%7}, {%8,%9}, {%0,%1,%2,%3};"
        : "+f"(c[0]), "+f"(c[1]), "+f"(c[2]), "+f"(c[3])
        : "r"(a[0]), "r"(a[1]), "r"(a[2]), "r"(a[3]), "r"(b0), "r"(b1));
}

template<typename OT>
__global__ __launch_bounds__(128, 2)
void k_gemm(const float* __restrict__ A, const float* __restrict__ Bt,
            OT* __restrict__ C, const float* __restrict__ bias, int M, int K) {
    extern __shared__ float smem[];

    const int tid  = threadIdx.x;
    const int lane = tid & 31;
    const int warp = tid >> 5;
    const int wm = warp & 1;
    const int wn = warp >> 1;
    const int g = lane >> 2;
    const int t = lane & 3;

    const int brow = blockIdx.y * BM;
    const int bcol = blockIdx.x * BN;
    const int rmaxA = M - brow;

    uint32_t sbase = (uint32_t)__cvta_generic_to_shared(smem);
    uint32_t sA[3], sB[3];
    #pragma unroll
    for (int s = 0; s < 3; s++) {
        sA[s] = sbase + (uint32_t)(s * (A_STG + B_STG)) * 4;
        sB[s] = sA[s] + A_STG * 4;
    }

    const float* Ag = A + (size_t)brow * K;
    const float* Bg = Bt + (size_t)bcol * K;

    const int la_row = wm * 64 + ((lane >> 3) & 1) * 8 + (lane & 7);
    const int la_col = ((lane >> 4) & 1) * 4;
    const int lb_row = wn * 64 + ((lane >> 4) & 1) * 8 + (lane & 7);
    const int lb_col = ((lane >> 3) & 1) * 4;

    const int KT = K >> 4;

    #define FILL(st, kt_) do {                                                  \
        int k0_ = (kt_) * BK;                                                   \
        _Pragma("unroll")                                                       \
        for (int u_ = 0; u_ < 4; u_++) {                                        \
            int ch_ = tid + u_ * 128;                                           \
            int r_ = ch_ >> 2, c_ = ch_ & 3;                                    \
            cp_async16(sA[st] + (r_ * PAD + c_ * 4) * 4,                        \
                       Ag + (size_t)r_ * K + k0_ + c_ * 4, r_ < rmaxA);         \
            cp_async16(sB[st] + (r_ * PAD + c_ * 4) * 4,                        \
                       Bg + (size_t)r_ * K + k0_ + c_ * 4, true);               \
        }                                                                       \
        CP_COMMIT();                                                            \
    } while (0)

    FILL(0, 0);
    FILL(1, 1);

    float acc[4][8][4];
    #pragma unroll
    for (int i = 0; i < 4; i++)
        #pragma unroll
        for (int j = 0; j < 8; j++)
            #pragma unroll
            for (int r = 0; r < 4; r++) acc[i][j][r] = 0.0f;

    for (int kt = 0; kt < KT; kt++) {
        if (kt + 1 < KT) { CP_WAIT(1); } else { CP_WAIT(0); }
        __syncthreads();

        int buf = kt % 3;
        uint32_t aab = sA[buf] + (la_row * PAD + la_col) * 4;
        uint32_t bab = sB[buf] + (lb_row * PAD + lb_col) * 4;

        #pragma unroll
        for (int ks = 0; ks < 2; ks++) {
            const int kb = ks * 8;
            uint32_t af[4][4];
            #pragma unroll
            for (int i = 0; i < 4; i++)
                ldsm_x4(af[i][0], af[i][1], af[i][2], af[i][3],
                        aab + (i * 16 * PAD + kb) * 4);
            uint32_t bf[4][4];
            #pragma unroll
            for (int j2 = 0; j2 < 4; j2++)
                ldsm_x4(bf[j2][0], bf[j2][1], bf[j2][2], bf[j2][3],
                        bab + (j2 * 16 * PAD + kb) * 4);
            #pragma unroll
            for (int i = 0; i < 4; i++) {
                #pragma unroll
                for (int j = 0; j < 8; j++) {
                    const uint32_t* bp = &bf[j >> 1][(j & 1) * 2];
                    mma_tf32(acc[i][j], af[i], bp[0], bp[1]);
                }
            }
        }

        if (kt + 2 < KT) {
            int nb = (kt + 2) % 3;
            FILL(nb, kt + 2);
        }
    }
    #undef FILL

    // epilogue: bias + relu; fp32 or fp16 store
    #pragma unroll
    for (int j = 0; j < 8; j++) {
        int c0 = bcol + wn * 64 + j * 8 + 2 * t;
        float2 bb = *(const float2*)(bias + c0);
        #pragma unroll
        for (int i = 0; i < 4; i++) {
            int r0 = brow + wm * 64 + i * 16 + g;
            int r1 = r0 + 8;
            float2 v0 = make_float2(fmaxf(acc[i][j][0] + bb.x, 0.0f),
                                    fmaxf(acc[i][j][1] + bb.y, 0.0f));
            float2 v1 = make_float2(fmaxf(acc[i][j][2] + bb.x, 0.0f),
                                    fmaxf(acc[i][j][3] + bb.y, 0.0f));
            if constexpr (sizeof(OT) == 2) {
                if (r0 < M) {
                    __half2 h = __floats2half2_rn(v0.x, v0.y);
                    *(uint32_t*)((__half*)C + (size_t)r0 * F_OUT + c0) =
                        *reinterpret_cast<uint32_t*>(&h);
                }
                if (r1 < M) {
                    __half2 h = __floats2half2_rn(v1.x, v1.y);
                    *(uint32_t*)((__half*)C + (size_t)r1 * F_OUT + c0) =
                        *reinterpret_cast<uint32_t*>(&h);
                }
            } else {
                if (r0 < M) *(float2*)((float*)C + (size_t)r0 * F_OUT + c0) = v0;
                if (r1 < M) *(float2*)((float*)C + (size_t)r1 * F_OUT + c0) = v1;
            }
        }
    }
}

// ---------------- segmented mean pooling + re-zero deg/cnt ---------------
// grid (4 f-chunks, 64 graphs), 64 threads: thread f = bx*256 + tid*4
__global__ __launch_bounds__(64)
void k_pool(const int* __restrict__ batch, const float* __restrict__ h,
            float* __restrict__ out) {
    int gph = blockIdx.y;
    int f = blockIdx.x * 256 + threadIdx.x * 4;

    // re-zero deg/cnt for the next graph replay (deterministic per call)
    int gt = (blockIdx.y * gridDim.x + blockIdx.x) * 64 + threadIdx.x;  // 0..16383
    for (int i = gt; i < N_NODES; i += 16384) { g_deg[i] = 0.0f; g_cnt_i[i] = 0; }

    int lo = 0, hi = N_NODES;
    while (lo < hi) { int m = (lo + hi) >> 1; if (batch[m] < gph) lo = m + 1; else hi = m; }
    int s = lo;
    hi = N_NODES;
    while (lo < hi) { int m = (lo + hi) >> 1; if (batch[m] < gph + 1) lo = m + 1; else hi = m; }
    int e = lo;

    float4 acc = make_float4(0.f, 0.f, 0.f, 0.f);
    for (int n = s; n < e; n++) {
        float4 v = *(const float4*)(h + (size_t)n * F_OUT + f);
        acc.x += v.x; acc.y += v.y; acc.z += v.z; acc.w += v.w;
    }
    float c = 1.0f / fmaxf((float)(e - s), 1.0f);
    acc.x *= c; acc.y *= c; acc.z *= c; acc.w *= c;
    *(float4*)(out + (size_t)gph * F_OUT + f) = acc;
}

// ---------------- launch ----------------
extern "C" void kernel_launch(void* const* d_in, const int* in_sizes, int n_in,
                              void* d_out, int out_size) {
    const float* x     = (const float*)d_in[0];
    const int*   ei    = (const int*)d_in[1];
    const float* ew    = (const float*)d_in[2];
    const int*   batch = (const int*)d_in[3];
    const float* W1    = (const float*)d_in[4];
    const float* b1    = (const float*)d_in[5];
    const float* W2    = (const float*)d_in[6];
    const float* b2    = (const float*)d_in[7];
    float* out = (float*)d_out;

    float *xw, *h1, *h2, *w1t, *w2t;
    cudaGetSymbolAddress((void**)&xw,  g_xw);
    cudaGetSymbolAddress((void**)&h1,  g_h1);
    cudaGetSymbolAddress((void**)&h2,  g_h2);
    cudaGetSymbolAddress((void**)&w1t, g_w1t);
    cudaGetSymbolAddress((void**)&w2t, g_w2t);

    __half* xh   = (__half*)h2;   // x fp16 (consumed by agg1 before gemm2 writes h2)
    __half* xw_h = (__half*)xw;   // gemm1 fp16 output

    static int smem_set = 0;
    if (!smem_set) {
        cudaFuncSetAttribute(k_gemm<float>,
                             cudaFuncAttributeMaxDynamicSharedMemorySize, GEMM_SMEM);
        cudaFuncSetAttribute(k_gemm<__half>,
                             cudaFuncAttributeMaxDynamicSharedMemorySize, GEMM_SMEM);
        smem_set = 1;
    }

    const int T = 256;
    dim3 gg(F_OUT / BN, (N_NODES + BM - 1) / BM);

    // L1: fused deg-count + x->fp16 (deg/cnt are pre-zeroed: static init / pool)
    k_pre<<<EDGE_BLOCKS + XCVT_BLOCKS, T>>>(ei, ew, x, xh);
    // L2: dinv + scan
    k_scan<<<1, 1024>>>();
    // L3: CSR scatter
    k_scatter<<<(N_EDGES + T - 1) / T, T>>>(ei, ew);
    // L4: layer-1 aggregation (fp16 gather) — profiled slot
    k_agg_h<F_IN><<<N_NODES, F_IN / 4>>>(xh, h1);
    // L5: weight transposes
    k_tr2<<<dim3(F_OUT / 32, F_OUT / 32, 2), dim3(32, 8)>>>(W1, w1t, W2, w2t);
    // L6: gemm1 -> fp16 xw (bias+relu fused)
    k_gemm<__half><<<gg, 128, GEMM_SMEM>>>(h1, w1t, xw_h, b1, N_NODES, F_IN);
    // L7: layer-2 aggregation (fp16 gather)
    k_agg_h<F_OUT><<<N_NODES, F_OUT / 4>>>(xw_h, h1);
    // L8: gemm2 -> fp32 h2 (bias+relu fused)
    k_gemm<float><<<gg, 128, GEMM_SMEM>>>(h1, w2t, h2, b2, N_NODES, F_OUT);
    // L9: mean pool + re-zero deg/cnt
    k_pool<<<dim3(4, N_GRAPHS), 64>>>(batch, h2, out);
}

// round 11
// speedup vs baseline: 1.7366x; 1.3949x over previous
#include <cuda_runtime.h>
#include <cuda_fp16.h>
#include <stdint.h>

#define N_NODES  20000
#define N_EDGES  320000
#define F_IN     512
#define F_OUT    1024
#define N_GRAPHS 64

// ---------------- scratch (static device globals; no allocations) ----------
__device__ float g_xw[(size_t)N_NODES * F_OUT];   // gemm1 out, fp16 [N,1024]
__device__ float g_h1[(size_t)N_NODES * F_OUT];   // agg outs, fp16 [N,512]/[N,1024]
__device__ float g_h2[(size_t)N_NODES * F_OUT];   // x fp16 early; gemm2 fp32 late
__device__ float g_w1t[(size_t)F_OUT * F_IN / 2]; // W1^T fp16 [1024,512]
__device__ float g_w2t[(size_t)F_OUT * F_OUT / 2];// W2^T fp16 [1024,1024]
__device__ float g_deg[N_NODES];                  // zero at entry (re-zeroed by pool)
__device__ float g_dinv[N_NODES];
__device__ int   g_cnt_i[N_NODES];                // zero at entry (re-zeroed by pool)
__device__ int   g_rank[N_NODES];
__device__ int   g_ptr[N_NODES + 1];
__device__ int   g_csr_src[N_EDGES];
__device__ float g_csr_norm[N_EDGES];

// ---------------- small helpers ----------------
__device__ __forceinline__ void cp_async16(uint32_t saddr, const void* gptr, bool pred) {
    int sz = pred ? 16 : 0;           // sz=0 -> zero-fill 16B
    asm volatile("cp.async.cg.shared.global [%0], [%1], 16, %2;\n"
                 :: "r"(saddr), "l"(gptr), "r"(sz));
}
#define CP_COMMIT() asm volatile("cp.async.commit_group;\n" ::)
#define CP_WAIT(n)  asm volatile("cp.async.wait_group %0;\n" :: "n"(n))

__device__ __forceinline__ void ldsm_x4(uint32_t& r0, uint32_t& r1, uint32_t& r2,
                                        uint32_t& r3, uint32_t addr) {
    asm volatile("ldmatrix.sync.aligned.m8n8.x4.shared.b16 {%0,%1,%2,%3}, [%4];"
                 : "=r"(r0), "=r"(r1), "=r"(r2), "=r"(r3) : "r"(addr));
}

// ---------------- L1: fused degree-count + x->fp16 convert ----------------
#define EDGE_BLOCKS ((N_EDGES + 255) / 256)               // 1250
#define XCVT4 (N_NODES * F_IN / 4)                        // float4 count
#define XCVT_BLOCKS ((XCVT4 + 255) / 256)                 // 10000

__global__ __launch_bounds__(256)
void k_pre(const int* __restrict__ ei, const float* __restrict__ ew,
           const float* __restrict__ x, __half* __restrict__ xh) {
    int b = blockIdx.x;
    if (b < EDGE_BLOCKS) {
        int e = b * 256 + threadIdx.x;
        if (e < N_EDGES) {
            int d = ei[N_EDGES + e];
            atomicAdd(&g_deg[d], ew[e]);
            atomicAdd(&g_cnt_i[d], 1);
        }
    } else {
        int i = (b - EDGE_BLOCKS) * 256 + threadIdx.x;
        if (i < XCVT4) {
            float4 v = ((const float4*)x)[i];
            __half2 h0 = __floats2half2_rn(v.x, v.y);
            __half2 h1 = __floats2half2_rn(v.z, v.w);
            uint2 p;
            p.x = *reinterpret_cast<uint32_t*>(&h0);
            p.y = *reinterpret_cast<uint32_t*>(&h1);
            ((uint2*)xh)[i] = p;
        }
    }
}

// L2: dinv (+1 self loop) + exclusive prefix sum -> ptr, rank
__global__ __launch_bounds__(1024)
void k_scan() {
    __shared__ int ps[1024];
    const int CH = (N_NODES + 1023) / 1024;  // 20
    int t = threadIdx.x;
    int base = t * CH;

    #pragma unroll
    for (int i = 0; i < CH; i++) {
        int idx = base + i;
        if (idx < N_NODES) {
            float d = g_deg[idx] + 1.0f;
            g_dinv[idx] = rsqrtf(d);
        }
    }

    int s = 0;
    #pragma unroll
    for (int i = 0; i < CH; i++) {
        int idx = base + i;
        if (idx < N_NODES) s += g_cnt_i[idx];
    }
    ps[t] = s;
    __syncthreads();
    for (int off = 1; off < 1024; off <<= 1) {
        int v = (t >= off) ? ps[t - off] : 0;
        __syncthreads();
        ps[t] += v;
        __syncthreads();
    }
    int run = ps[t] - s;
    #pragma unroll
    for (int i = 0; i < CH; i++) {
        int idx = base + i;
        if (idx < N_NODES) { g_ptr[idx] = run; g_rank[idx] = run; run += g_cnt_i[idx]; }
    }
    if (t == 1023) g_ptr[N_NODES] = run;
}

// L3: CSR scatter
__global__ void k_scatter(const int* __restrict__ ei, const float* __restrict__ ew) {
    int e = blockIdx.x * blockDim.x + threadIdx.x;
    if (e < N_EDGES) {
        int s = ei[e];
        int d = ei[N_EDGES + e];
        int pos = atomicAdd(&g_rank[d], 1);
        g_csr_src[pos]  = s;
        g_csr_norm[pos] = g_dinv[s] * ew[e] * g_dinv[d];
    }
}

// ---------------- fused CSR aggregation, fp16 in -> fp16 out --------------
template<int F>
__global__ __launch_bounds__(F / 4)
void k_agg_h(const __half* __restrict__ in, __half* __restrict__ out) {
    int n = blockIdx.x;
    int f = threadIdx.x * 4;

    float di = g_dinv[n];
    float s = di * di;

    uint2 raw = *(const uint2*)(in + (size_t)n * F + f);
    float2 p0 = __half22float2(*reinterpret_cast<__half2*>(&raw.x));
    float2 p1 = __half22float2(*reinterpret_cast<__half2*>(&raw.y));
    float4 acc = make_float4(s * p0.x, s * p0.y, s * p1.x, s * p1.y);

    int e0 = g_ptr[n], e1 = g_ptr[n + 1];
    for (int e = e0; e < e1; e++) {
        int src = __ldg(&g_csr_src[e]);
        float w = __ldg(&g_csr_norm[e]);
        uint2 r = *(const uint2*)(in + (size_t)src * F + f);
        float2 u0 = __half22float2(*reinterpret_cast<__half2*>(&r.x));
        float2 u1 = __half22float2(*reinterpret_cast<__half2*>(&r.y));
        acc.x = fmaf(w, u0.x, acc.x);
        acc.y = fmaf(w, u0.y, acc.y);
        acc.z = fmaf(w, u1.x, acc.z);
        acc.w = fmaf(w, u1.y, acc.w);
    }
    __half2 o0 = __floats2half2_rn(acc.x, acc.y);
    __half2 o1 = __floats2half2_rn(acc.z, acc.w);
    uint2 p;
    p.x = *reinterpret_cast<uint32_t*>(&o0);
    p.y = *reinterpret_cast<uint32_t*>(&o1);
    *(uint2*)(out + (size_t)n * F + f) = p;
}

// ---------------- weight transposes (fp32 -> fp16) ----------------
__device__ __forceinline__ void tr_tile(const float* __restrict__ W,
                                        __half* __restrict__ Wt, int R, int C) {
    __shared__ float s[32][33];
    int x  = blockIdx.x * 32 + threadIdx.x;
    int y0 = blockIdx.y * 32;
    #pragma unroll
    for (int i = 0; i < 32; i += 8)
        s[threadIdx.y + i][threadIdx.x] = W[(size_t)(y0 + threadIdx.y + i) * C + x];
    __syncthreads();
    int xt  = blockIdx.y * 32 + threadIdx.x;
    int yt0 = blockIdx.x * 32;
    #pragma unroll
    for (int i = 0; i < 32; i += 8)
        Wt[(size_t)(yt0 + threadIdx.y + i) * R + xt] = __float2half_rn(s[threadIdx.x][threadIdx.y + i]);
}

__global__ __launch_bounds__(256)
void k_tr2(const float* __restrict__ W1, __half* __restrict__ W1t,
           const float* __restrict__ W2, __half* __restrict__ W2t) {
    if (blockIdx.z == 0) {
        if (blockIdx.y < F_IN / 32) tr_tile(W1, W1t, F_IN, F_OUT);
    } else {
        tr_tile(W2, W2t, F_OUT, F_OUT);
    }
}

// ---------------- fp16 mma.sync GEMM, 128x128, 4 warps 2x2, 2 CTAs/SM ----
// C = relu(A @ W + bias); A fp16 [M,K], Bt = W^T fp16 [1024,K] row-major.
// m16n8k16, warp tile 64x64, BK=32 halfs, 3-stage cp.async.
// smem rows: 32 halfs padded to 40 (80B) -> ldmatrix conflict-free pattern.
#define BM 128
#define BN 128
#define BKH 32                                // K elems (halfs) per tile
#define PADH 40                               // halfs per smem row
#define A_STG (BM * PADH)                     // 5120 halfs
#define B_STG (BN * PADH)
#define GEMM_SMEM (3 * (A_STG + B_STG) * 2)   // 61440 B

__device__ __forceinline__ void mma_f16(float c[4], const uint32_t a[4],
                                        uint32_t b0, uint32_t b1) {
    asm volatile(
        "mma.sync.aligned.m16n8k16.row.col.f32.f16.f16.f32 "
        "{%0,%1,%2,%3}, {%4,%5,%6,%7}, {%8,%9}, {%0,%1,%2,%3};"
        : "+f"(c[0]), "+f"(c[1]), "+f"(c[2]), "+f"(c[3])
        : "r"(a[0]), "r"(a[1]), "r"(a[2]), "r"(a[3]), "r"(b0), "r"(b1));
}

template<typename OT>
__global__ __launch_bounds__(128, 2)
void k_gemm(const __half* __restrict__ A, const __half* __restrict__ Bt,
            OT* __restrict__ C, const float* __restrict__ bias, int M, int K) {
    extern __shared__ __half smem[];

    const int tid  = threadIdx.x;
    const int lane = tid & 31;
    const int warp = tid >> 5;
    const int wm = warp & 1;
    const int wn = warp >> 1;
    const int g = lane >> 2;
    const int t = lane & 3;

    const int brow = blockIdx.y * BM;
    const int bcol = blockIdx.x * BN;
    const int rmaxA = M - brow;

    uint32_t sbase = (uint32_t)__cvta_generic_to_shared(smem);
    uint32_t sA[3], sB[3];
    #pragma unroll
    for (int s = 0; s < 3; s++) {
        sA[s] = sbase + (uint32_t)(s * (A_STG + B_STG)) * 2;
        sB[s] = sA[s] + A_STG * 2;
    }

    const __half* Ag = A + (size_t)brow * K;
    const __half* Bg = Bt + (size_t)bcol * K;

    // ldmatrix lane addressing (16B col units = 8 halfs)
    const int la_row = wm * 64 + ((lane >> 3) & 1) * 8 + (lane & 7);
    const int la_col = ((lane >> 4) & 1) * 8;   // halfs
    const int lb_row = wn * 64 + ((lane >> 4) & 1) * 8 + (lane & 7);
    const int lb_col = ((lane >> 3) & 1) * 8;   // halfs

    const int KT = K >> 5;   // k-tiles of 32 halfs

    // fill: A and B each 128 rows x 4 16B-chunks = 512 chunks, 4/thread
    #define FILL(st, kt_) do {                                                  \
        int k0_ = (kt_) * BKH;                                                  \
        _Pragma("unroll")                                                       \
        for (int u_ = 0; u_ < 4; u_++) {                                        \
            int ch_ = tid + u_ * 128;                                           \
            int r_ = ch_ >> 2, c_ = ch_ & 3;                                    \
            cp_async16(sA[st] + (r_ * PADH + c_ * 8) * 2,                       \
                       Ag + (size_t)r_ * K + k0_ + c_ * 8, r_ < rmaxA);         \
            cp_async16(sB[st] + (r_ * PADH + c_ * 8) * 2,                       \
                       Bg + (size_t)r_ * K + k0_ + c_ * 8, true);               \
        }                                                                       \
        CP_COMMIT();                                                            \
    } while (0)

    FILL(0, 0);
    FILL(1, 1);

    float acc[4][8][4];
    #pragma unroll
    for (int i = 0; i < 4; i++)
        #pragma unroll
        for (int j = 0; j < 8; j++)
            #pragma unroll
            for (int r = 0; r < 4; r++) acc[i][j][r] = 0.0f;

    for (int kt = 0; kt < KT; kt++) {
        if (kt + 1 < KT) { CP_WAIT(1); } else { CP_WAIT(0); }
        __syncthreads();

        int buf = kt % 3;
        uint32_t aab = sA[buf] + (la_row * PADH + la_col) * 2;
        uint32_t bab = sB[buf] + (lb_row * PADH + lb_col) * 2;

        #pragma unroll
        for (int ks = 0; ks < 2; ks++) {
            const int kb = ks * 16;   // halfs
            uint32_t af[4][4];
            #pragma unroll
            for (int i = 0; i < 4; i++)
                ldsm_x4(af[i][0], af[i][1], af[i][2], af[i][3],
                        aab + (i * 16 * PADH + kb) * 2);
            uint32_t bf[4][4];
            #pragma unroll
            for (int j2 = 0; j2 < 4; j2++)
                ldsm_x4(bf[j2][0], bf[j2][1], bf[j2][2], bf[j2][3],
                        bab + (j2 * 16 * PADH + kb) * 2);
            #pragma unroll
            for (int i = 0; i < 4; i++) {
                #pragma unroll
                for (int j = 0; j < 8; j++) {
                    const uint32_t* bp = &bf[j >> 1][(j & 1) * 2];
                    mma_f16(acc[i][j], af[i], bp[0], bp[1]);
                }
            }
        }

        if (kt + 2 < KT) {
            int nb = (kt + 2) % 3;
            FILL(nb, kt + 2);
        }
    }
    #undef FILL

    // epilogue: bias + relu; fp32 or fp16 store
    #pragma unroll
    for (int j = 0; j < 8; j++) {
        int c0 = bcol + wn * 64 + j * 8 + 2 * t;
        float2 bb = *(const float2*)(bias + c0);
        #pragma unroll
        for (int i = 0; i < 4; i++) {
            int r0 = brow + wm * 64 + i * 16 + g;
            int r1 = r0 + 8;
            float2 v0 = make_float2(fmaxf(acc[i][j][0] + bb.x, 0.0f),
                                    fmaxf(acc[i][j][1] + bb.y, 0.0f));
            float2 v1 = make_float2(fmaxf(acc[i][j][2] + bb.x, 0.0f),
                                    fmaxf(acc[i][j][3] + bb.y, 0.0f));
            if constexpr (sizeof(OT) == 2) {
                if (r0 < M) {
                    __half2 h = __floats2half2_rn(v0.x, v0.y);
                    *(uint32_t*)((__half*)C + (size_t)r0 * F_OUT + c0) =
                        *reinterpret_cast<uint32_t*>(&h);
                }
                if (r1 < M) {
                    __half2 h = __floats2half2_rn(v1.x, v1.y);
                    *(uint32_t*)((__half*)C + (size_t)r1 * F_OUT + c0) =
                        *reinterpret_cast<uint32_t*>(&h);
                }
            } else {
                if (r0 < M) *(float2*)((float*)C + (size_t)r0 * F_OUT + c0) = v0;
                if (r1 < M) *(float2*)((float*)C + (size_t)r1 * F_OUT + c0) = v1;
            }
        }
    }
}

// ---------------- segmented mean pooling + re-zero deg/cnt ---------------
__global__ __launch_bounds__(64)
void k_pool(const int* __restrict__ batch, const float* __restrict__ h,
            float* __restrict__ out) {
    int gph = blockIdx.y;
    int f = blockIdx.x * 256 + threadIdx.x * 4;

    int gt = (blockIdx.y * gridDim.x + blockIdx.x) * 64 + threadIdx.x;
    for (int i = gt; i < N_NODES; i += 16384) { g_deg[i] = 0.0f; g_cnt_i[i] = 0; }

    int lo = 0, hi = N_NODES;
    while (lo < hi) { int m = (lo + hi) >> 1; if (batch[m] < gph) lo = m + 1; else hi = m; }
    int s = lo;
    hi = N_NODES;
    while (lo < hi) { int m = (lo + hi) >> 1; if (batch[m] < gph + 1) lo = m + 1; else hi = m; }
    int e = lo;

    float4 acc = make_float4(0.f, 0.f, 0.f, 0.f);
    for (int n = s; n < e; n++) {
        float4 v = *(const float4*)(h + (size_t)n * F_OUT + f);
        acc.x += v.x; acc.y += v.y; acc.z += v.z; acc.w += v.w;
    }
    float c = 1.0f / fmaxf((float)(e - s), 1.0f);
    acc.x *= c; acc.y *= c; acc.z *= c; acc.w *= c;
    *(float4*)(out + (size_t)gph * F_OUT + f) = acc;
}

// ---------------- launch ----------------
extern "C" void kernel_launch(void* const* d_in, const int* in_sizes, int n_in,
                              void* d_out, int out_size) {
    const float* x     = (const float*)d_in[0];
    const int*   ei    = (const int*)d_in[1];
    const float* ew    = (const float*)d_in[2];
    const int*   batch = (const int*)d_in[3];
    const float* W1    = (const float*)d_in[4];
    const float* b1    = (const float*)d_in[5];
    const float* W2    = (const float*)d_in[6];
    const float* b2    = (const float*)d_in[7];
    float* out = (float*)d_out;

    float *xw, *h1, *h2, *w1t, *w2t;
    cudaGetSymbolAddress((void**)&xw,  g_xw);
    cudaGetSymbolAddress((void**)&h1,  g_h1);
    cudaGetSymbolAddress((void**)&h2,  g_h2);
    cudaGetSymbolAddress((void**)&w1t, g_w1t);
    cudaGetSymbolAddress((void**)&w2t, g_w2t);

    __half* xh    = (__half*)h2;    // x fp16 [N,512]
    __half* aggh  = (__half*)h1;    // agg outputs fp16
    __half* xw_h  = (__half*)xw;    // gemm1 fp16 output [N,1024]
    __half* w1th  = (__half*)w1t;
    __half* w2th  = (__half*)w2t;

    static int smem_set = 0;
    if (!smem_set) {
        cudaFuncSetAttribute(k_gemm<float>,
                             cudaFuncAttributeMaxDynamicSharedMemorySize, GEMM_SMEM);
        cudaFuncSetAttribute(k_gemm<__half>,
                             cudaFuncAttributeMaxDynamicSharedMemorySize, GEMM_SMEM);
        smem_set = 1;
    }

    const int T = 256;
    dim3 gg(F_OUT / BN, (N_NODES + BM - 1) / BM);

    // L1: fused deg-count + x->fp16
    k_pre<<<EDGE_BLOCKS + XCVT_BLOCKS, T>>>(ei, ew, x, xh);
    // L2: dinv + scan
    k_scan<<<1, 1024>>>();
    // L3: CSR scatter
    k_scatter<<<(N_EDGES + T - 1) / T, T>>>(ei, ew);
    // L4: layer-1 aggregation (fp16 -> fp16)
    k_agg_h<F_IN><<<N_NODES, F_IN / 4>>>(xh, aggh);
    // L5: weight transposes (fp32 -> fp16)
    k_tr2<<<dim3(F_OUT / 32, F_OUT / 32, 2), dim3(32, 8)>>>(W1, w1th, W2, w2th);
    // L6: gemm1 (fp16 mma) -> fp16 xw, bias+relu fused
    k_gemm<__half><<<gg, 128, GEMM_SMEM>>>(aggh, w1th, xw_h, b1, N_NODES, F_IN);
    // L7: layer-2 aggregation (fp16 -> fp16)
    k_agg_h<F_OUT><<<N_NODES, F_OUT / 4>>>(xw_h, aggh);
    // L8: gemm2 (fp16 mma) -> fp32 h2, bias+relu fused
    k_gemm<float><<<gg, 128, GEMM_SMEM>>>(aggh, w2th, h2, b2, N_NODES, F_OUT);
    // L9: mean pool + re-zero deg/cnt
    k_pool<<<dim3(4, N_GRAPHS), 64>>>(batch, h2, out);
}

// round 12
// speedup vs baseline: 1.8141x; 1.0446x over previous
#include <cuda_runtime.h>
#include <cuda_fp16.h>
#include <stdint.h>

#define N_NODES  20000
#define N_EDGES  320000
#define F_IN     512
#define F_OUT    1024
#define N_GRAPHS 64

// ---------------- scratch (static device globals; no allocations) ----------
__device__ float g_xw[(size_t)N_NODES * F_OUT];   // gemm1 out, fp16 [N,1024]
__device__ float g_h1[(size_t)N_NODES * F_OUT];   // agg outs, fp16 [N,512]/[N,1024]
__device__ float g_h2[(size_t)N_NODES * F_OUT];   // x fp16 early; gemm2 fp32 late
__device__ float g_w1t[(size_t)F_OUT * F_IN / 2]; // W1^T fp16 [1024,512]
__device__ float g_w2t[(size_t)F_OUT * F_OUT / 2];// W2^T fp16 [1024,1024]
__device__ float g_deg[N_NODES];                  // zero at entry (re-zeroed by pool)
__device__ float g_dinv[N_NODES];
__device__ int   g_cnt_i[N_NODES];                // zero at entry (re-zeroed by pool)
__device__ int   g_rank[N_NODES];
__device__ int   g_ptr[N_NODES + 1];
__device__ int   g_csr_src[N_EDGES];
__device__ float g_csr_norm[N_EDGES];

// ---------------- small helpers ----------------
__device__ __forceinline__ void cp_async16(uint32_t saddr, const void* gptr, bool pred) {
    int sz = pred ? 16 : 0;           // sz=0 -> zero-fill 16B
    asm volatile("cp.async.cg.shared.global [%0], [%1], 16, %2;\n"
                 :: "r"(saddr), "l"(gptr), "r"(sz));
}
#define CP_COMMIT() asm volatile("cp.async.commit_group;\n" ::)
#define CP_WAIT(n)  asm volatile("cp.async.wait_group %0;\n" :: "n"(n))

__device__ __forceinline__ void ldsm_x4(uint32_t& r0, uint32_t& r1, uint32_t& r2,
                                        uint32_t& r3, uint32_t addr) {
    asm volatile("ldmatrix.sync.aligned.m8n8.x4.shared.b16 {%0,%1,%2,%3}, [%4];"
                 : "=r"(r0), "=r"(r1), "=r"(r2), "=r"(r3) : "r"(addr));
}

// ---------------- L1: fused degree-count + x->fp16 convert ----------------
#define EDGE_BLOCKS ((N_EDGES + 255) / 256)               // 1250
#define XCVT4 (N_NODES * F_IN / 4)                        // float4 count
#define XCVT_BLOCKS ((XCVT4 + 255) / 256)                 // 10000

__global__ __launch_bounds__(256)
void k_pre(const int* __restrict__ ei, const float* __restrict__ ew,
           const float* __restrict__ x, __half* __restrict__ xh) {
    int b = blockIdx.x;
    if (b < EDGE_BLOCKS) {
        int e = b * 256 + threadIdx.x;
        if (e < N_EDGES) {
            int d = ei[N_EDGES + e];
            atomicAdd(&g_deg[d], ew[e]);
            atomicAdd(&g_cnt_i[d], 1);
        }
    } else {
        int i = (b - EDGE_BLOCKS) * 256 + threadIdx.x;
        if (i < XCVT4) {
            float4 v = ((const float4*)x)[i];
            __half2 h0 = __floats2half2_rn(v.x, v.y);
            __half2 h1 = __floats2half2_rn(v.z, v.w);
            uint2 p;
            p.x = *reinterpret_cast<uint32_t*>(&h0);
            p.y = *reinterpret_cast<uint32_t*>(&h1);
            ((uint2*)xh)[i] = p;
        }
    }
}

// L2: dinv (+1 self loop) + exclusive prefix sum -> ptr, rank
__global__ __launch_bounds__(1024)
void k_scan() {
    __shared__ int ps[1024];
    const int CH = (N_NODES + 1023) / 1024;  // 20
    int t = threadIdx.x;
    int base = t * CH;

    #pragma unroll
    for (int i = 0; i < CH; i++) {
        int idx = base + i;
        if (idx < N_NODES) {
            float d = g_deg[idx] + 1.0f;
            g_dinv[idx] = rsqrtf(d);
        }
    }

    int s = 0;
    #pragma unroll
    for (int i = 0; i < CH; i++) {
        int idx = base + i;
        if (idx < N_NODES) s += g_cnt_i[idx];
    }
    ps[t] = s;
    __syncthreads();
    for (int off = 1; off < 1024; off <<= 1) {
        int v = (t >= off) ? ps[t - off] : 0;
        __syncthreads();
        ps[t] += v;
        __syncthreads();
    }
    int run = ps[t] - s;
    #pragma unroll
    for (int i = 0; i < CH; i++) {
        int idx = base + i;
        if (idx < N_NODES) { g_ptr[idx] = run; g_rank[idx] = run; run += g_cnt_i[idx]; }
    }
    if (t == 1023) g_ptr[N_NODES] = run;
}

// L3: CSR scatter
__global__ void k_scatter(const int* __restrict__ ei, const float* __restrict__ ew) {
    int e = blockIdx.x * blockDim.x + threadIdx.x;
    if (e < N_EDGES) {
        int s = ei[e];
        int d = ei[N_EDGES + e];
        int pos = atomicAdd(&g_rank[d], 1);
        g_csr_src[pos]  = s;
        g_csr_norm[pos] = g_dinv[s] * ew[e] * g_dinv[d];
    }
}

// ---------------- fused CSR aggregation, fp16 in -> fp16 out --------------
template<int F>
__global__ __launch_bounds__(F / 4)
void k_agg_h(const __half* __restrict__ in, __half* __restrict__ out) {
    int n = blockIdx.x;
    int f = threadIdx.x * 4;

    float di = g_dinv[n];
    float s = di * di;

    uint2 raw = *(const uint2*)(in + (size_t)n * F + f);
    float2 p0 = __half22float2(*reinterpret_cast<__half2*>(&raw.x));
    float2 p1 = __half22float2(*reinterpret_cast<__half2*>(&raw.y));
    float4 acc = make_float4(s * p0.x, s * p0.y, s * p1.x, s * p1.y);

    int e0 = g_ptr[n], e1 = g_ptr[n + 1];
    for (int e = e0; e < e1; e++) {
        int src = __ldg(&g_csr_src[e]);
        float w = __ldg(&g_csr_norm[e]);
        uint2 r = *(const uint2*)(in + (size_t)src * F + f);
        float2 u0 = __half22float2(*reinterpret_cast<__half2*>(&r.x));
        float2 u1 = __half22float2(*reinterpret_cast<__half2*>(&r.y));
        acc.x = fmaf(w, u0.x, acc.x);
        acc.y = fmaf(w, u0.y, acc.y);
        acc.z = fmaf(w, u1.x, acc.z);
        acc.w = fmaf(w, u1.y, acc.w);
    }
    __half2 o0 = __floats2half2_rn(acc.x, acc.y);
    __half2 o1 = __floats2half2_rn(acc.z, acc.w);
    uint2 p;
    p.x = *reinterpret_cast<uint32_t*>(&o0);
    p.y = *reinterpret_cast<uint32_t*>(&o1);
    *(uint2*)(out + (size_t)n * F + f) = p;
}

// ---------------- weight transposes (fp32 -> fp16) ----------------
__device__ __forceinline__ void tr_tile(const float* __restrict__ W,
                                        __half* __restrict__ Wt, int R, int C) {
    __shared__ float s[32][33];
    int x  = blockIdx.x * 32 + threadIdx.x;
    int y0 = blockIdx.y * 32;
    #pragma unroll
    for (int i = 0; i < 32; i += 8)
        s[threadIdx.y + i][threadIdx.x] = W[(size_t)(y0 + threadIdx.y + i) * C + x];
    __syncthreads();
    int xt  = blockIdx.y * 32 + threadIdx.x;
    int yt0 = blockIdx.x * 32;
    #pragma unroll
    for (int i = 0; i < 32; i += 8)
        Wt[(size_t)(yt0 + threadIdx.y + i) * R + xt] = __float2half_rn(s[threadIdx.x][threadIdx.y + i]);
}

__global__ __launch_bounds__(256)
void k_tr2(const float* __restrict__ W1, __half* __restrict__ W1t,
           const float* __restrict__ W2, __half* __restrict__ W2t) {
    if (blockIdx.z == 0) {
        if (blockIdx.y < F_IN / 32) tr_tile(W1, W1t, F_IN, F_OUT);
    } else {
        tr_tile(W2, W2t, F_OUT, F_OUT);
    }
}

// ---------------- fp16 mma.sync GEMM, 128x128, BK=64, 4 warps 2x2 --------
// C = relu(A @ W + bias); A fp16 [M,K], Bt = W^T fp16 [1024,K] row-major.
// m16n8k16, warp tile 64x64, 3-stage cp.async, 2 CTAs/SM.
// smem rows: 64 halfs padded to 72 (144B): 8-row ldmatrix offsets 16i mod 128
// all distinct -> conflict-free.
#define BM 128
#define BN 128
#define BKH 64                                // K halfs per stage
#define PADH 72                               // halfs per smem row
#define A_STG (BM * PADH)                     // 9216 halfs
#define B_STG (BN * PADH)
#define GEMM_SMEM (3 * (A_STG + B_STG) * 2)   // 110592 B

__device__ __forceinline__ void mma_f16(float c[4], const uint32_t a[4],
                                        uint32_t b0, uint32_t b1) {
    asm volatile(
        "mma.sync.aligned.m16n8k16.row.col.f32.f16.f16.f32 "
        "{%0,%1,%2,%3}, {%4,%5,%6,%7}, {%8,%9}, {%0,%1,%2,%3};"
        : "+f"(c[0]), "+f"(c[1]), "+f"(c[2]), "+f"(c[3])
        : "r"(a[0]), "r"(a[1]), "r"(a[2]), "r"(a[3]), "r"(b0), "r"(b1));
}

template<typename OT>
__global__ __launch_bounds__(128, 2)
void k_gemm(const __half* __restrict__ A, const __half* __restrict__ Bt,
            OT* __restrict__ C, const float* __restrict__ bias, int M, int K) {
    extern __shared__ __half smem[];

    const int tid  = threadIdx.x;
    const int lane = tid & 31;
    const int warp = tid >> 5;
    const int wm = warp & 1;
    const int wn = warp >> 1;
    const int g = lane >> 2;
    const int t = lane & 3;

    const int brow = blockIdx.y * BM;
    const int bcol = blockIdx.x * BN;
    const int rmaxA = M - brow;

    uint32_t sbase = (uint32_t)__cvta_generic_to_shared(smem);
    uint32_t sA[3], sB[3];
    #pragma unroll
    for (int s = 0; s < 3; s++) {
        sA[s] = sbase + (uint32_t)(s * (A_STG + B_STG)) * 2;
        sB[s] = sA[s] + A_STG * 2;
    }

    const __half* Ag = A + (size_t)brow * K;
    const __half* Bg = Bt + (size_t)bcol * K;

    // ldmatrix lane addressing (16B col units = 8 halfs)
    const int la_row = wm * 64 + ((lane >> 3) & 1) * 8 + (lane & 7);
    const int la_col = ((lane >> 4) & 1) * 8;   // halfs
    const int lb_row = wn * 64 + ((lane >> 4) & 1) * 8 + (lane & 7);
    const int lb_col = ((lane >> 3) & 1) * 8;   // halfs

    const int KT = K >> 6;   // k-tiles of 64 halfs

    // fill: A and B each 128 rows x 8 16B-chunks = 1024 chunks, 8/thread
    #define FILL(st, kt_) do {                                                  \
        int k0_ = (kt_) * BKH;                                                  \
        _Pragma("unroll")                                                       \
        for (int u_ = 0; u_ < 8; u_++) {                                        \
            int ch_ = tid + u_ * 128;                                           \
            int r_ = ch_ >> 3, c_ = ch_ & 7;                                    \
            cp_async16(sA[st] + (r_ * PADH + c_ * 8) * 2,                       \
                       Ag + (size_t)r_ * K + k0_ + c_ * 8, r_ < rmaxA);         \
            cp_async16(sB[st] + (r_ * PADH + c_ * 8) * 2,                       \
                       Bg + (size_t)r_ * K + k0_ + c_ * 8, true);               \
        }                                                                       \
        CP_COMMIT();                                                            \
    } while (0)

    FILL(0, 0);
    FILL(1, 1);

    float acc[4][8][4];
    #pragma unroll
    for (int i = 0; i < 4; i++)
        #pragma unroll
        for (int j = 0; j < 8; j++)
            #pragma unroll
            for (int r = 0; r < 4; r++) acc[i][j][r] = 0.0f;

    for (int kt = 0; kt < KT; kt++) {
        if (kt + 1 < KT) { CP_WAIT(1); } else { CP_WAIT(0); }
        __syncthreads();

        int buf = kt % 3;
        uint32_t aab = sA[buf] + (la_row * PADH + la_col) * 2;
        uint32_t bab = sB[buf] + (lb_row * PADH + lb_col) * 2;

        #pragma unroll
        for (int ks = 0; ks < 4; ks++) {
            const int kb = ks * 16;   // halfs
            uint32_t af[4][4];
            #pragma unroll
            for (int i = 0; i < 4; i++)
                ldsm_x4(af[i][0], af[i][1], af[i][2], af[i][3],
                        aab + (i * 16 * PADH + kb) * 2);
            uint32_t bf[4][4];
            #pragma unroll
            for (int j2 = 0; j2 < 4; j2++)
                ldsm_x4(bf[j2][0], bf[j2][1], bf[j2][2], bf[j2][3],
                        bab + (j2 * 16 * PADH + kb) * 2);
            #pragma unroll
            for (int i = 0; i < 4; i++) {
                #pragma unroll
                for (int j = 0; j < 8; j++) {
                    const uint32_t* bp = &bf[j >> 1][(j & 1) * 2];
                    mma_f16(acc[i][j], af[i], bp[0], bp[1]);
                }
            }
        }

        if (kt + 2 < KT) {
            int nb = (kt + 2) % 3;
            FILL(nb, kt + 2);
        }
    }
    #undef FILL

    // epilogue: bias + relu; fp32 or fp16 store
    #pragma unroll
    for (int j = 0; j < 8; j++) {
        int c0 = bcol + wn * 64 + j * 8 + 2 * t;
        float2 bb = *(const float2*)(bias + c0);
        #pragma unroll
        for (int i = 0; i < 4; i++) {
            int r0 = brow + wm * 64 + i * 16 + g;
            int r1 = r0 + 8;
            float2 v0 = make_float2(fmaxf(acc[i][j][0] + bb.x, 0.0f),
                                    fmaxf(acc[i][j][1] + bb.y, 0.0f));
            float2 v1 = make_float2(fmaxf(acc[i][j][2] + bb.x, 0.0f),
                                    fmaxf(acc[i][j][3] + bb.y, 0.0f));
            if constexpr (sizeof(OT) == 2) {
                if (r0 < M) {
                    __half2 h = __floats2half2_rn(v0.x, v0.y);
                    *(uint32_t*)((__half*)C + (size_t)r0 * F_OUT + c0) =
                        *reinterpret_cast<uint32_t*>(&h);
                }
                if (r1 < M) {
                    __half2 h = __floats2half2_rn(v1.x, v1.y);
                    *(uint32_t*)((__half*)C + (size_t)r1 * F_OUT + c0) =
                        *reinterpret_cast<uint32_t*>(&h);
                }
            } else {
                if (r0 < M) *(float2*)((float*)C + (size_t)r0 * F_OUT + c0) = v0;
                if (r1 < M) *(float2*)((float*)C + (size_t)r1 * F_OUT + c0) = v1;
            }
        }
    }
}

// ---------------- segmented mean pooling + re-zero deg/cnt ---------------
__global__ __launch_bounds__(64)
void k_pool(const int* __restrict__ batch, const float* __restrict__ h,
            float* __restrict__ out) {
    int gph = blockIdx.y;
    int f = blockIdx.x * 256 + threadIdx.x * 4;

    int gt = (blockIdx.y * gridDim.x + blockIdx.x) * 64 + threadIdx.x;
    for (int i = gt; i < N_NODES; i += 16384) { g_deg[i] = 0.0f; g_cnt_i[i] = 0; }

    int lo = 0, hi = N_NODES;
    while (lo < hi) { int m = (lo + hi) >> 1; if (batch[m] < gph) lo = m + 1; else hi = m; }
    int s = lo;
    hi = N_NODES;
    while (lo < hi) { int m = (lo + hi) >> 1; if (batch[m] < gph + 1) lo = m + 1; else hi = m; }
    int e = lo;

    float4 acc = make_float4(0.f, 0.f, 0.f, 0.f);
    for (int n = s; n < e; n++) {
        float4 v = *(const float4*)(h + (size_t)n * F_OUT + f);
        acc.x += v.x; acc.y += v.y; acc.z += v.z; acc.w += v.w;
    }
    float c = 1.0f / fmaxf((float)(e - s), 1.0f);
    acc.x *= c; acc.y *= c; acc.z *= c; acc.w *= c;
    *(float4*)(out + (size_t)gph * F_OUT + f) = acc;
}

// ---------------- launch ----------------
extern "C" void kernel_launch(void* const* d_in, const int* in_sizes, int n_in,
                              void* d_out, int out_size) {
    const float* x     = (const float*)d_in[0];
    const int*   ei    = (const int*)d_in[1];
    const float* ew    = (const float*)d_in[2];
    const int*   batch = (const int*)d_in[3];
    const float* W1    = (const float*)d_in[4];
    const float* b1    = (const float*)d_in[5];
    const float* W2    = (const float*)d_in[6];
    const float* b2    = (const float*)d_in[7];
    float* out = (float*)d_out;

    float *xw, *h1, *h2, *w1t, *w2t;
    cudaGetSymbolAddress((void**)&xw,  g_xw);
    cudaGetSymbolAddress((void**)&h1,  g_h1);
    cudaGetSymbolAddress((void**)&h2,  g_h2);
    cudaGetSymbolAddress((void**)&w1t, g_w1t);
    cudaGetSymbolAddress((void**)&w2t, g_w2t);

    __half* xh    = (__half*)h2;
    __half* aggh  = (__half*)h1;
    __half* xw_h  = (__half*)xw;
    __half* w1th  = (__half*)w1t;
    __half* w2th  = (__half*)w2t;

    static int smem_set = 0;
    if (!smem_set) {
        cudaFuncSetAttribute(k_gemm<float>,
                             cudaFuncAttributeMaxDynamicSharedMemorySize, GEMM_SMEM);
        cudaFuncSetAttribute(k_gemm<__half>,
                             cudaFuncAttributeMaxDynamicSharedMemorySize, GEMM_SMEM);
        smem_set = 1;
    }

    const int T = 256;
    dim3 gg(F_OUT / BN, (N_NODES + BM - 1) / BM);

    // L1: fused deg-count + x->fp16
    k_pre<<<EDGE_BLOCKS + XCVT_BLOCKS, T>>>(ei, ew, x, xh);
    // L2: dinv + scan
    k_scan<<<1, 1024>>>();
    // L3: CSR scatter
    k_scatter<<<(N_EDGES + T - 1) / T, T>>>(ei, ew);
    // L4: layer-1 aggregation (fp16 -> fp16)
    k_agg_h<F_IN><<<N_NODES, F_IN / 4>>>(xh, aggh);
    // L5: weight transposes (fp32 -> fp16)
    k_tr2<<<dim3(F_OUT / 32, F_OUT / 32, 2), dim3(32, 8)>>>(W1, w1th, W2, w2th);
    // L6: gemm1 (fp16 mma, BK=64) -> fp16 xw, bias+relu fused
    k_gemm<__half><<<gg, 128, GEMM_SMEM>>>(aggh, w1th, xw_h, b1, N_NODES, F_IN);
    // L7: layer-2 aggregation (fp16 -> fp16)
    k_agg_h<F_OUT><<<N_NODES, F_OUT / 4>>>(xw_h, aggh);
    // L8: gemm2 (fp16 mma, BK=64) -> fp32 h2, bias+relu fused
    k_gemm<float><<<gg, 128, GEMM_SMEM>>>(aggh, w2th, h2, b2, N_NODES, F_OUT);
    // L9: mean pool + re-zero deg/cnt
    k_pool<<<dim3(4, N_GRAPHS), 64>>>(batch, h2, out);
}

// round 13
// speedup vs baseline: 1.9042x; 1.0497x over previous
#include <cuda_runtime.h>
#include <cuda_fp16.h>
#include <stdint.h>

#define N_NODES  20000
#define N_EDGES  320000
#define F_IN     512
#define F_OUT    1024
#define N_GRAPHS 64

// ---------------- scratch (static device globals; no allocations) ----------
__device__ float g_xw[(size_t)N_NODES * F_OUT];   // gemm1 out, fp16 [N,1024]
__device__ float g_h1[(size_t)N_NODES * F_OUT];   // agg outs, fp16 [N,512]/[N,1024]
__device__ float g_h2[(size_t)N_NODES * F_OUT];   // x fp16 early; gemm2 fp16 late
__device__ float g_w1t[(size_t)F_OUT * F_IN / 2]; // W1^T fp16 [1024,512]
__device__ float g_w2t[(size_t)F_OUT * F_OUT / 2];// W2^T fp16 [1024,1024]
__device__ float g_deg[N_NODES];                  // zero at entry (re-zeroed by pool)
__device__ float g_dinv[N_NODES];
__device__ int   g_cnt_i[N_NODES];                // zero at entry (re-zeroed by pool)
__device__ int   g_rank[N_NODES];
__device__ int   g_ptr[N_NODES + 1];
__device__ int   g_csr_src[N_EDGES];
__device__ float g_csr_norm[N_EDGES];

// ---------------- small helpers ----------------
__device__ __forceinline__ void cp_async16(uint32_t saddr, const void* gptr, bool pred) {
    int sz = pred ? 16 : 0;           // sz=0 -> zero-fill 16B
    asm volatile("cp.async.cg.shared.global [%0], [%1], 16, %2;\n"
                 :: "r"(saddr), "l"(gptr), "r"(sz));
}
#define CP_COMMIT() asm volatile("cp.async.commit_group;\n" ::)
#define CP_WAIT(n)  asm volatile("cp.async.wait_group %0;\n" :: "n"(n))

__device__ __forceinline__ void ldsm_x4(uint32_t& r0, uint32_t& r1, uint32_t& r2,
                                        uint32_t& r3, uint32_t addr) {
    asm volatile("ldmatrix.sync.aligned.m8n8.x4.shared.b16 {%0,%1,%2,%3}, [%4];"
                 : "=r"(r0), "=r"(r1), "=r"(r2), "=r"(r3) : "r"(addr));
}

// ---------------- L1: fused degree-count + x->fp16 convert ----------------
#define EDGE_BLOCKS ((N_EDGES + 255) / 256)               // 1250
#define XCVT4 (N_NODES * F_IN / 4)                        // float4 count
#define XCVT_BLOCKS ((XCVT4 + 255) / 256)                 // 10000

__global__ __launch_bounds__(256)
void k_pre(const int* __restrict__ ei, const float* __restrict__ ew,
           const float* __restrict__ x, __half* __restrict__ xh) {
    int b = blockIdx.x;
    if (b < EDGE_BLOCKS) {
        int e = b * 256 + threadIdx.x;
        if (e < N_EDGES) {
            int d = ei[N_EDGES + e];
            atomicAdd(&g_deg[d], ew[e]);
            atomicAdd(&g_cnt_i[d], 1);
        }
    } else {
        int i = (b - EDGE_BLOCKS) * 256 + threadIdx.x;
        if (i < XCVT4) {
            float4 v = ((const float4*)x)[i];
            __half2 h0 = __floats2half2_rn(v.x, v.y);
            __half2 h1 = __floats2half2_rn(v.z, v.w);
            uint2 p;
            p.x = *reinterpret_cast<uint32_t*>(&h0);
            p.y = *reinterpret_cast<uint32_t*>(&h1);
            ((uint2*)xh)[i] = p;
        }
    }
}

// L2: dinv (+1 self loop) + exclusive prefix sum -> ptr, rank (warp-shuffle)
__global__ __launch_bounds__(1024)
void k_scan() {
    __shared__ int wsum[32];
    const int CH = (N_NODES + 1023) / 1024;  // 20
    int t = threadIdx.x;
    int lane = t & 31;
    int wid  = t >> 5;
    int base = t * CH;

    int s = 0;
    #pragma unroll
    for (int i = 0; i < CH; i++) {
        int idx = base + i;
        if (idx < N_NODES) {
            float d = g_deg[idx] + 1.0f;
            g_dinv[idx] = rsqrtf(d);
            s += g_cnt_i[idx];
        }
    }

    // inclusive warp scan of s
    int v = s;
    #pragma unroll
    for (int off = 1; off < 32; off <<= 1) {
        int n = __shfl_up_sync(0xffffffffu, v, off);
        if (lane >= off) v += n;
    }
    if (lane == 31) wsum[wid] = v;
    __syncthreads();
    if (wid == 0) {
        int w = (lane < 32) ? wsum[lane] : 0;
        #pragma unroll
        for (int off = 1; off < 32; off <<= 1) {
            int n = __shfl_up_sync(0xffffffffu, w, off);
            if (lane >= off) w += n;
        }
        wsum[lane] = w;
    }
    __syncthreads();
    int warp_excl = (wid > 0) ? wsum[wid - 1] : 0;
    int run = warp_excl + v - s;   // exclusive prefix for this thread's chunk

    #pragma unroll
    for (int i = 0; i < CH; i++) {
        int idx = base + i;
        if (idx < N_NODES) { g_ptr[idx] = run; g_rank[idx] = run; run += g_cnt_i[idx]; }
    }
    if (t == 1023) g_ptr[N_NODES] = run;
}

// L3: CSR scatter
__global__ void k_scatter(const int* __restrict__ ei, const float* __restrict__ ew) {
    int e = blockIdx.x * blockDim.x + threadIdx.x;
    if (e < N_EDGES) {
        int s = ei[e];
        int d = ei[N_EDGES + e];
        int pos = atomicAdd(&g_rank[d], 1);
        g_csr_src[pos]  = s;
        g_csr_norm[pos] = g_dinv[s] * ew[e] * g_dinv[d];
    }
}

// ---------------- fused CSR aggregation, fp16 in -> fp16 out --------------
template<int F>
__global__ __launch_bounds__(F / 4)
void k_agg_h(const __half* __restrict__ in, __half* __restrict__ out) {
    int n = blockIdx.x;
    int f = threadIdx.x * 4;

    float di = g_dinv[n];
    float s = di * di;

    uint2 raw = *(const uint2*)(in + (size_t)n * F + f);
    float2 p0 = __half22float2(*reinterpret_cast<__half2*>(&raw.x));
    float2 p1 = __half22float2(*reinterpret_cast<__half2*>(&raw.y));
    float4 acc = make_float4(s * p0.x, s * p0.y, s * p1.x, s * p1.y);

    int e0 = g_ptr[n], e1 = g_ptr[n + 1];
    for (int e = e0; e < e1; e++) {
        int src = __ldg(&g_csr_src[e]);
        float w = __ldg(&g_csr_norm[e]);
        uint2 r = *(const uint2*)(in + (size_t)src * F + f);
        float2 u0 = __half22float2(*reinterpret_cast<__half2*>(&r.x));
        float2 u1 = __half22float2(*reinterpret_cast<__half2*>(&r.y));
        acc.x = fmaf(w, u0.x, acc.x);
        acc.y = fmaf(w, u0.y, acc.y);
        acc.z = fmaf(w, u1.x, acc.z);
        acc.w = fmaf(w, u1.y, acc.w);
    }
    __half2 o0 = __floats2half2_rn(acc.x, acc.y);
    __half2 o1 = __floats2half2_rn(acc.z, acc.w);
    uint2 p;
    p.x = *reinterpret_cast<uint32_t*>(&o0);
    p.y = *reinterpret_cast<uint32_t*>(&o1);
    *(uint2*)(out + (size_t)n * F + f) = p;
}

// ---------------- weight transposes (fp32 -> fp16) ----------------
__device__ __forceinline__ void tr_tile(const float* __restrict__ W,
                                        __half* __restrict__ Wt, int R, int C) {
    __shared__ float s[32][33];
    int x  = blockIdx.x * 32 + threadIdx.x;
    int y0 = blockIdx.y * 32;
    #pragma unroll
    for (int i = 0; i < 32; i += 8)
        s[threadIdx.y + i][threadIdx.x] = W[(size_t)(y0 + threadIdx.y + i) * C + x];
    __syncthreads();
    int xt  = blockIdx.y * 32 + threadIdx.x;
    int yt0 = blockIdx.x * 32;
    #pragma unroll
    for (int i = 0; i < 32; i += 8)
        Wt[(size_t)(yt0 + threadIdx.y + i) * R + xt] = __float2half_rn(s[threadIdx.x][threadIdx.y + i]);
}

__global__ __launch_bounds__(256)
void k_tr2(const float* __restrict__ W1, __half* __restrict__ W1t,
           const float* __restrict__ W2, __half* __restrict__ W2t) {
    if (blockIdx.z == 0) {
        if (blockIdx.y < F_IN / 32) tr_tile(W1, W1t, F_IN, F_OUT);
    } else {
        tr_tile(W2, W2t, F_OUT, F_OUT);
    }
}

// ---------------- fp16 mma.sync GEMM, 128x128, BK=64, 4 warps 2x2 --------
#define BM 128
#define BN 128
#define BKH 64                                // K halfs per stage
#define PADH 72                               // halfs per smem row (144B)
#define A_STG (BM * PADH)
#define B_STG (BN * PADH)
#define GEMM_SMEM (3 * (A_STG + B_STG) * 2)   // 110592 B

__device__ __forceinline__ void mma_f16(float c[4], const uint32_t a[4],
                                        uint32_t b0, uint32_t b1) {
    asm volatile(
        "mma.sync.aligned.m16n8k16.row.col.f32.f16.f16.f32 "
        "{%0,%1,%2,%3}, {%4,%5,%6,%7}, {%8,%9}, {%0,%1,%2,%3};"
        : "+f"(c[0]), "+f"(c[1]), "+f"(c[2]), "+f"(c[3])
        : "r"(a[0]), "r"(a[1]), "r"(a[2]), "r"(a[3]), "r"(b0), "r"(b1));
}

template<typename OT>
__global__ __launch_bounds__(128, 2)
void k_gemm(const __half* __restrict__ A, const __half* __restrict__ Bt,
            OT* __restrict__ C, const float* __restrict__ bias, int M, int K) {
    extern __shared__ __half smem[];

    const int tid  = threadIdx.x;
    const int lane = tid & 31;
    const int warp = tid >> 5;
    const int wm = warp & 1;
    const int wn = warp >> 1;
    const int g = lane >> 2;
    const int t = lane & 3;

    const int brow = blockIdx.y * BM;
    const int bcol = blockIdx.x * BN;
    const int rmaxA = M - brow;

    uint32_t sbase = (uint32_t)__cvta_generic_to_shared(smem);
    uint32_t sA[3], sB[3];
    #pragma unroll
    for (int s = 0; s < 3; s++) {
        sA[s] = sbase + (uint32_t)(s * (A_STG + B_STG)) * 2;
        sB[s] = sA[s] + A_STG * 2;
    }

    const __half* Ag = A + (size_t)brow * K;
    const __half* Bg = Bt + (size_t)bcol * K;

    const int la_row = wm * 64 + ((lane >> 3) & 1) * 8 + (lane & 7);
    const int la_col = ((lane >> 4) & 1) * 8;   // halfs
    const int lb_row = wn * 64 + ((lane >> 4) & 1) * 8 + (lane & 7);
    const int lb_col = ((lane >> 3) & 1) * 8;   // halfs

    const int KT = K >> 6;   // k-tiles of 64 halfs

    #define FILL(st, kt_) do {                                                  \
        int k0_ = (kt_) * BKH;                                                  \
        _Pragma("unroll")                                                       \
        for (int u_ = 0; u_ < 8; u_++) {                                        \
            int ch_ = tid + u_ * 128;                                           \
            int r_ = ch_ >> 3, c_ = ch_ & 7;                                    \
            cp_async16(sA[st] + (r_ * PADH + c_ * 8) * 2,                       \
                       Ag + (size_t)r_ * K + k0_ + c_ * 8, r_ < rmaxA);         \
            cp_async16(sB[st] + (r_ * PADH + c_ * 8) * 2,                       \
                       Bg + (size_t)r_ * K + k0_ + c_ * 8, true);               \
        }                                                                       \
        CP_COMMIT();                                                            \
    } while (0)

    FILL(0, 0);
    FILL(1, 1);

    float acc[4][8][4];
    #pragma unroll
    for (int i = 0; i < 4; i++)
        #pragma unroll
        for (int j = 0; j < 8; j++)
            #pragma unroll
            for (int r = 0; r < 4; r++) acc[i][j][r] = 0.0f;

    for (int kt = 0; kt < KT; kt++) {
        if (kt + 1 < KT) { CP_WAIT(1); } else { CP_WAIT(0); }
        __syncthreads();

        // hoist next fill: stage (kt+2)%3 == (kt-1)%3, free after the barrier
        if (kt + 2 < KT) {
            int nb = (kt + 2) % 3;
            FILL(nb, kt + 2);
        }

        int buf = kt % 3;
        uint32_t aab = sA[buf] + (la_row * PADH + la_col) * 2;
        uint32_t bab = sB[buf] + (lb_row * PADH + lb_col) * 2;

        #pragma unroll
        for (int ks = 0; ks < 4; ks++) {
            const int kb = ks * 16;   // halfs
            uint32_t af[4][4];
            #pragma unroll
            for (int i = 0; i < 4; i++)
                ldsm_x4(af[i][0], af[i][1], af[i][2], af[i][3],
                        aab + (i * 16 * PADH + kb) * 2);
            uint32_t bf[4][4];
            #pragma unroll
            for (int j2 = 0; j2 < 4; j2++)
                ldsm_x4(bf[j2][0], bf[j2][1], bf[j2][2], bf[j2][3],
                        bab + (j2 * 16 * PADH + kb) * 2);
            #pragma unroll
            for (int i = 0; i < 4; i++) {
                #pragma unroll
                for (int j = 0; j < 8; j++) {
                    const uint32_t* bp = &bf[j >> 1][(j & 1) * 2];
                    mma_f16(acc[i][j], af[i], bp[0], bp[1]);
                }
            }
        }
    }
    #undef FILL

    // epilogue: bias + relu; fp32 or fp16 store
    #pragma unroll
    for (int j = 0; j < 8; j++) {
        int c0 = bcol + wn * 64 + j * 8 + 2 * t;
        float2 bb = *(const float2*)(bias + c0);
        #pragma unroll
        for (int i = 0; i < 4; i++) {
            int r0 = brow + wm * 64 + i * 16 + g;
            int r1 = r0 + 8;
            float2 v0 = make_float2(fmaxf(acc[i][j][0] + bb.x, 0.0f),
                                    fmaxf(acc[i][j][1] + bb.y, 0.0f));
            float2 v1 = make_float2(fmaxf(acc[i][j][2] + bb.x, 0.0f),
                                    fmaxf(acc[i][j][3] + bb.y, 0.0f));
            if constexpr (sizeof(OT) == 2) {
                if (r0 < M) {
                    __half2 h = __floats2half2_rn(v0.x, v0.y);
                    *(uint32_t*)((__half*)C + (size_t)r0 * F_OUT + c0) =
                        *reinterpret_cast<uint32_t*>(&h);
                }
                if (r1 < M) {
                    __half2 h = __floats2half2_rn(v1.x, v1.y);
                    *(uint32_t*)((__half*)C + (size_t)r1 * F_OUT + c0) =
                        *reinterpret_cast<uint32_t*>(&h);
                }
            } else {
                if (r0 < M) *(float2*)((float*)C + (size_t)r0 * F_OUT + c0) = v0;
                if (r1 < M) *(float2*)((float*)C + (size_t)r1 * F_OUT + c0) = v1;
            }
        }
    }
}

// ---------------- segmented mean pooling (fp16 in) + re-zero deg/cnt -----
__global__ __launch_bounds__(64)
void k_pool(const int* __restrict__ batch, const __half* __restrict__ h,
            float* __restrict__ out) {
    int gph = blockIdx.y;
    int f = blockIdx.x * 256 + threadIdx.x * 4;

    int gt = (blockIdx.y * gridDim.x + blockIdx.x) * 64 + threadIdx.x;
    for (int i = gt; i < N_NODES; i += 16384) { g_deg[i] = 0.0f; g_cnt_i[i] = 0; }

    int lo = 0, hi = N_NODES;
    while (lo < hi) { int m = (lo + hi) >> 1; if (batch[m] < gph) lo = m + 1; else hi = m; }
    int s = lo;
    hi = N_NODES;
    while (lo < hi) { int m = (lo + hi) >> 1; if (batch[m] < gph + 1) lo = m + 1; else hi = m; }
    int e = lo;

    float4 acc = make_float4(0.f, 0.f, 0.f, 0.f);
    for (int n = s; n < e; n++) {
        uint2 r = *(const uint2*)(h + (size_t)n * F_OUT + f);
        float2 u0 = __half22float2(*reinterpret_cast<__half2*>(&r.x));
        float2 u1 = __half22float2(*reinterpret_cast<__half2*>(&r.y));
        acc.x += u0.x; acc.y += u0.y; acc.z += u1.x; acc.w += u1.y;
    }
    float c = 1.0f / fmaxf((float)(e - s), 1.0f);
    acc.x *= c; acc.y *= c; acc.z *= c; acc.w *= c;
    *(float4*)(out + (size_t)gph * F_OUT + f) = acc;
}

// ---------------- launch ----------------
extern "C" void kernel_launch(void* const* d_in, const int* in_sizes, int n_in,
                              void* d_out, int out_size) {
    const float* x     = (const float*)d_in[0];
    const int*   ei    = (const int*)d_in[1];
    const float* ew    = (const float*)d_in[2];
    const int*   batch = (const int*)d_in[3];
    const float* W1    = (const float*)d_in[4];
    const float* b1    = (const float*)d_in[5];
    const float* W2    = (const float*)d_in[6];
    const float* b2    = (const float*)d_in[7];
    float* out = (float*)d_out;

    float *xw, *h1, *h2, *w1t, *w2t;
    cudaGetSymbolAddress((void**)&xw,  g_xw);
    cudaGetSymbolAddress((void**)&h1,  g_h1);
    cudaGetSymbolAddress((void**)&h2,  g_h2);
    cudaGetSymbolAddress((void**)&w1t, g_w1t);
    cudaGetSymbolAddress((void**)&w2t, g_w2t);

    __half* xh    = (__half*)h2;     // x fp16 [N,512]
    __half* aggh  = (__half*)h1;     // agg outputs fp16
    __half* xw_h  = (__half*)xw;     // gemm1 fp16 output [N,1024]
    __half* h2h   = (__half*)h2;     // gemm2 fp16 output [N,1024] (xh dead by then)
    __half* w1th  = (__half*)w1t;
    __half* w2th  = (__half*)w2t;

    static int smem_set = 0;
    if (!smem_set) {
        cudaFuncSetAttribute(k_gemm<__half>,
                             cudaFuncAttributeMaxDynamicSharedMemorySize, GEMM_SMEM);
        smem_set = 1;
    }

    const int T = 256;
    dim3 gg(F_OUT / BN, (N_NODES + BM - 1) / BM);

    // L1: fused deg-count + x->fp16
    k_pre<<<EDGE_BLOCKS + XCVT_BLOCKS, T>>>(ei, ew, x, xh);
    // L2: dinv + warp-shuffle scan
    k_scan<<<1, 1024>>>();
    // L3: CSR scatter
    k_scatter<<<(N_EDGES + T - 1) / T, T>>>(ei, ew);
    // L4: layer-1 aggregation (fp16 -> fp16)
    k_agg_h<F_IN><<<N_NODES, F_IN / 4>>>(xh, aggh);
    // L5: weight transposes (fp32 -> fp16)
    k_tr2<<<dim3(F_OUT / 32, F_OUT / 32, 2), dim3(32, 8)>>>(W1, w1th, W2, w2th);
    // L6: gemm1 (fp16 mma, BK=64) -> fp16 xw, bias+relu fused
    k_gemm<__half><<<gg, 128, GEMM_SMEM>>>(aggh, w1th, xw_h, b1, N_NODES, F_IN);
    // L7: layer-2 aggregation (fp16 -> fp16)
    k_agg_h<F_OUT><<<N_NODES, F_OUT / 4>>>(xw_h, aggh);
    // L8: gemm2 (fp16 mma, BK=64) -> fp16 h2, bias+relu fused
    k_gemm<__half><<<gg, 128, GEMM_SMEM>>>(aggh, w2th, h2h, b2, N_NODES, F_OUT);
    // L9: mean pool (fp16 in) + re-zero deg/cnt
    k_pool<<<dim3(4, N_GRAPHS), 64>>>(batch, h2h, out);
}